// round 2
// baseline (speedup 1.0000x reference)
#include <cuda_runtime.h>
#include <cstdint>

// Problem constants
#define BB 2
#define SS 2048
#define DD 1024
#define HH 16
#define HDIM 64
#define MTOT (BB * SS) // 4096

// ---------------------------------------------------------------------------
// Scratch (device globals; allocation inside kernel_launch is forbidden)
// ---------------------------------------------------------------------------
__device__ float g_Q[(size_t)MTOT * DD];   // projected Q   [4096,1024]
__device__ float g_K[(size_t)MTOT * DD];   // compacted projected K (per-batch region b*2048..)
__device__ float g_V[(size_t)MTOT * DD];   // compacted projected V
__device__ float g_A[(size_t)MTOT * DD];   // attention output before Wo
__device__ int   g_idx[MTOT];              // compacted key row ids (global row b*S+s)
__device__ int   g_cnt[BB];                // valid key count per batch

// ---------------------------------------------------------------------------
// Kernel 1: deterministic mask compaction (prefix scan, no atomics)
// valid(b,s) = !key_padding_mask && !attn_mask  (masks arrive as int32)
// ---------------------------------------------------------------------------
__global__ __launch_bounds__(1024) void build_idx_kernel(
    const int* __restrict__ kp, const int* __restrict__ am,
    int* __restrict__ idx, int* __restrict__ counts)
{
    __shared__ int ssum[1024];
    const int b = blockIdx.x;
    const int t = threadIdx.x;
    const int base = b * SS;
    const int s0 = 2 * t, s1 = 2 * t + 1;
    int v0 = (kp[base + s0] == 0 && am[base + s0] == 0) ? 1 : 0;
    int v1 = (kp[base + s1] == 0 && am[base + s1] == 0) ? 1 : 0;
    ssum[t] = v0 + v1;
    __syncthreads();
    // Hillis-Steele inclusive scan over 1024 partials
    for (int off = 1; off < 1024; off <<= 1) {
        int add = (t >= off) ? ssum[t - off] : 0;
        int val = ssum[t];
        __syncthreads();
        ssum[t] = val + add;
        __syncthreads();
    }
    int excl = ssum[t] - (v0 + v1);
    if (v0) idx[base + excl]      = base + s0;
    if (v1) idx[base + excl + v0] = base + s1;
    if (t == 1023) counts[b] = ssum[1023];
}

// ---------------------------------------------------------------------------
// Kernel 2: SGEMM  C[m,n] = sum_k A[m,k] * W[n,k] + bias[n]
// M=4096, N=1024, K=1024.  Block tile 128x128, BK=8, 256 thr, 8x8/thread.
// Optional gather mode: A row = gather[m], rows with (m%2048)>=counts[m/2048]
// are skipped (block-level early exit when fully invalid).
// ---------------------------------------------------------------------------
__global__ __launch_bounds__(256) void gemm_tn_kernel(
    const float* __restrict__ A, const float* __restrict__ W,
    const float* __restrict__ bias, float* __restrict__ C,
    const int* __restrict__ gather, const int* __restrict__ counts)
{
    __shared__ float As[8][132];
    __shared__ float Ws[8][132];
    const int nBase = blockIdx.x * 128;
    const int mBase = blockIdx.y * 128;
    if (gather) {
        int bb = mBase >> 11;
        if ((mBase & 2047) >= counts[bb]) return; // whole block invalid
    }
    const int t  = threadIdx.x;
    const int tx = t & 15, ty = t >> 4;
    const int lRow = t >> 1;
    const int lC4  = (t & 1) * 4;

    int srcRow; bool rowOk = true;
    {
        int m = mBase + lRow;
        if (gather) {
            int bb = m >> 11, jj = m & 2047;
            rowOk = jj < counts[bb];
            srcRow = rowOk ? gather[m] : 0;
        } else {
            srcRow = m;
        }
    }
    const float* Aptr = A + (size_t)srcRow * DD + lC4;
    const float* Wptr = W + (size_t)(nBase + lRow) * DD + lC4;

    float acc[8][8];
#pragma unroll
    for (int i = 0; i < 8; i++)
#pragma unroll
        for (int j = 0; j < 8; j++) acc[i][j] = 0.f;

    float4 pa = rowOk ? *(const float4*)(Aptr) : make_float4(0.f, 0.f, 0.f, 0.f);
    float4 pw = *(const float4*)(Wptr);

    for (int k0 = 0; k0 < DD; k0 += 8) {
        // stage (transposed: As[k][m]) — conflict-free scalar stores
        As[lC4 + 0][lRow] = pa.x; As[lC4 + 1][lRow] = pa.y;
        As[lC4 + 2][lRow] = pa.z; As[lC4 + 3][lRow] = pa.w;
        Ws[lC4 + 0][lRow] = pw.x; Ws[lC4 + 1][lRow] = pw.y;
        Ws[lC4 + 2][lRow] = pw.z; Ws[lC4 + 3][lRow] = pw.w;
        __syncthreads();
        if (k0 + 8 < DD) { // register prefetch of next K-slab
            pa = rowOk ? *(const float4*)(Aptr + k0 + 8) : make_float4(0.f, 0.f, 0.f, 0.f);
            pw = *(const float4*)(Wptr + k0 + 8);
        }
#pragma unroll
        for (int kk = 0; kk < 8; kk++) {
            float4 a0 = *(const float4*)&As[kk][ty * 8];
            float4 a1 = *(const float4*)&As[kk][ty * 8 + 4];
            float4 b0 = *(const float4*)&Ws[kk][tx * 8];
            float4 b1 = *(const float4*)&Ws[kk][tx * 8 + 4];
            float av[8] = {a0.x, a0.y, a0.z, a0.w, a1.x, a1.y, a1.z, a1.w};
            float bv[8] = {b0.x, b0.y, b0.z, b0.w, b1.x, b1.y, b1.z, b1.w};
#pragma unroll
            for (int i = 0; i < 8; i++)
#pragma unroll
                for (int j = 0; j < 8; j++) acc[i][j] += av[i] * bv[j];
        }
        __syncthreads();
    }

#pragma unroll
    for (int i = 0; i < 8; i++) {
        int m = mBase + ty * 8 + i;
        bool ok = true;
        if (gather) ok = (m & 2047) < counts[m >> 11];
        if (ok) {
            float* cp = C + (size_t)m * DD + nBase + tx * 8;
            const float* bp = bias + nBase + tx * 8;
            float4 o0 = make_float4(acc[i][0] + bp[0], acc[i][1] + bp[1],
                                    acc[i][2] + bp[2], acc[i][3] + bp[3]);
            float4 o1 = make_float4(acc[i][4] + bp[4], acc[i][5] + bp[5],
                                    acc[i][6] + bp[6], acc[i][7] + bp[7]);
            *(float4*)cp = o0;
            *(float4*)(cp + 4) = o1;
        }
    }
}

// ---------------------------------------------------------------------------
// Kernel 3: flash attention over compacted keys.
// Grid (32 qblocks, 16 heads, 2 batches), 256 threads, 64x64 tiles.
// Smem: Qs(16KB) + KPs(16KB: K tile then P tile) + Vs(16KB) = exactly 48KB.
// K tile stored XOR-swizzled in 16B units: conflict-free LDS.128 on both
// the transpose-free store and the strided 4-row reads.
// ---------------------------------------------------------------------------
__global__ __launch_bounds__(256) void attn_kernel(
    const float* __restrict__ Q, const float* __restrict__ K,
    const float* __restrict__ V, float* __restrict__ O,
    const int* __restrict__ counts)
{
    __shared__ float Qs[64 * 64];
    __shared__ float KPs[64 * 64];
    __shared__ float Vs[64 * 64];

    const int qb = blockIdx.x, h = blockIdx.y, b = blockIdx.z;
    const int t  = threadIdx.x;
    const int tx = t & 15, ty = t >> 4;
    const int q0 = qb * 64;
    const int cnt = counts[b];

    // load Q tile (scaled by 1/sqrt(64) = 0.125)
    const float* Qbase = Q + (size_t)(b * SS + q0) * DD + h * HDIM;
    for (int i = t; i < 1024; i += 256) {
        int r = i >> 4, c4 = (i & 15) << 2;
        float4 v = *(const float4*)(Qbase + (size_t)r * DD + c4);
        *(float4*)&Qs[r * 64 + c4] =
            make_float4(v.x * 0.125f, v.y * 0.125f, v.z * 0.125f, v.w * 0.125f);
    }

    float m_i[4], l_i[4], acc[4][4];
#pragma unroll
    for (int i = 0; i < 4; i++) {
        m_i[i] = -1e30f; l_i[i] = 0.f;
#pragma unroll
        for (int j = 0; j < 4; j++) acc[i][j] = 0.f;
    }
    __syncthreads();

    const int nb = (cnt + 63) >> 6;
    for (int kb = 0; kb < nb; kb++) {
        const int kbase = kb * 64;
        // load K tile, XOR-swizzled per 16B chunk
        const float* Kb = K + (size_t)(b * SS + kbase) * DD + h * HDIM;
        for (int i = t; i < 1024; i += 256) {
            int r = i >> 4, q = i & 15;
            float4 v = *(const float4*)(Kb + (size_t)r * DD + 4 * q);
            *(float4*)&KPs[r * 64 + 4 * (q ^ ((r >> 2) & 7))] = v;
        }
        __syncthreads();

        // S = Q K^T  (4x4 per thread; rows ty*4+i, key-cols 4*tx+j)
        float s[4][4];
#pragma unroll
        for (int i = 0; i < 4; i++)
#pragma unroll
            for (int j = 0; j < 4; j++) s[i][j] = 0.f;
#pragma unroll
        for (int d4 = 0; d4 < 16; d4++) {
            float4 qv[4];
#pragma unroll
            for (int i = 0; i < 4; i++)
                qv[i] = *(const float4*)&Qs[(ty * 4 + i) * 64 + 4 * d4];
#pragma unroll
            for (int j = 0; j < 4; j++) {
                int kr = 4 * tx + j;
                float4 kv = *(const float4*)&KPs[kr * 64 + 4 * (d4 ^ (tx & 7))];
#pragma unroll
                for (int i = 0; i < 4; i++)
                    s[i][j] += qv[i].x * kv.x + qv[i].y * kv.y +
                               qv[i].z * kv.z + qv[i].w * kv.w;
            }
        }

        // tail masking (only keys >= cnt; all earlier keys are valid by construction)
#pragma unroll
        for (int j = 0; j < 4; j++) {
            if (kbase + 4 * tx + j >= cnt) {
#pragma unroll
                for (int i = 0; i < 4; i++) s[i][j] = -1e30f;
            }
        }

        // online softmax: row max/sum reduced across the 16-thread tx group
        float rmax[4], rsum[4];
#pragma unroll
        for (int i = 0; i < 4; i++) {
            rmax[i] = -1e30f;
#pragma unroll
            for (int j = 0; j < 4; j++) rmax[i] = fmaxf(rmax[i], s[i][j]);
        }
#pragma unroll
        for (int o = 1; o < 16; o <<= 1)
#pragma unroll
            for (int i = 0; i < 4; i++)
                rmax[i] = fmaxf(rmax[i], __shfl_xor_sync(0xffffffffu, rmax[i], o));
#pragma unroll
        for (int i = 0; i < 4; i++) {
            float mn = fmaxf(m_i[i], rmax[i]);
            float corr = __expf(m_i[i] - mn);
            m_i[i] = mn;
            float rs = 0.f;
#pragma unroll
            for (int j = 0; j < 4; j++) {
                float p = __expf(s[i][j] - mn);
                s[i][j] = p;
                rs += p;
            }
            rsum[i] = rs;
            l_i[i] *= corr;
#pragma unroll
            for (int j = 0; j < 4; j++) acc[i][j] *= corr;
        }
#pragma unroll
        for (int o = 1; o < 16; o <<= 1)
#pragma unroll
            for (int i = 0; i < 4; i++)
                rsum[i] += __shfl_xor_sync(0xffffffffu, rsum[i], o);
#pragma unroll
        for (int i = 0; i < 4; i++) l_i[i] += rsum[i];

        __syncthreads(); // all threads done reading K tile

        // write P into KPs (natural layout), load V tile
#pragma unroll
        for (int i = 0; i < 4; i++)
            *(float4*)&KPs[(ty * 4 + i) * 64 + 4 * tx] =
                make_float4(s[i][0], s[i][1], s[i][2], s[i][3]);
        const float* Vb = V + (size_t)(b * SS + kbase) * DD + h * HDIM;
        for (int i2 = t; i2 < 1024; i2 += 256) {
            int r = i2 >> 4, q = i2 & 15;
            *(float4*)&Vs[r * 64 + 4 * q] = *(const float4*)(Vb + (size_t)r * DD + 4 * q);
        }
        __syncthreads();

        // O += P V   (columns 4*tx+j contiguous -> LDS.128 on V)
#pragma unroll
        for (int k = 0; k < 64; k++) {
            float4 vv = *(const float4*)&Vs[k * 64 + 4 * tx];
#pragma unroll
            for (int i = 0; i < 4; i++) {
                float p = KPs[(ty * 4 + i) * 64 + k];
                acc[i][0] += p * vv.x; acc[i][1] += p * vv.y;
                acc[i][2] += p * vv.z; acc[i][3] += p * vv.w;
            }
        }
        __syncthreads(); // P/V consumed before next iteration overwrites
    }

#pragma unroll
    for (int i = 0; i < 4; i++) {
        float inv = 1.0f / l_i[i];
        int row = b * SS + q0 + ty * 4 + i;
        *(float4*)&O[(size_t)row * DD + h * HDIM + 4 * tx] =
            make_float4(acc[i][0] * inv, acc[i][1] * inv,
                        acc[i][2] * inv, acc[i][3] * inv);
    }
}

// ---------------------------------------------------------------------------
// Launch — inputs classified by element count (robust to is_casual presence
// and exact ordering quirks):
//   4194304 -> query, key, value (in order)
//   4096    -> key_padding_mask, attn_mask (in order, int32)
//   1048576 -> Wq, Wk, Wv, Wo (in order)
//   1024    -> bq, bk, bv, bo (in order)
//   1       -> is_casual (ignored)
// ---------------------------------------------------------------------------
extern "C" void kernel_launch(void* const* d_in, const int* in_sizes, int n_in,
                              void* d_out, int out_size)
{
    (void)out_size;
    const float* qkv[3]  = {nullptr, nullptr, nullptr};
    const int*   masks[2] = {nullptr, nullptr};
    const float* Ws[4]   = {nullptr, nullptr, nullptr, nullptr};
    const float* bs[4]   = {nullptr, nullptr, nullptr, nullptr};
    int nqkv = 0, nmask = 0, nW = 0, nb = 0;
    for (int i = 0; i < n_in; i++) {
        int sz = in_sizes[i];
        if (sz == MTOT * DD && nqkv < 3)      qkv[nqkv++] = (const float*)d_in[i];
        else if (sz == MTOT && nmask < 2)     masks[nmask++] = (const int*)d_in[i];
        else if (sz == DD * DD && nW < 4)     Ws[nW++] = (const float*)d_in[i];
        else if (sz == DD && nb < 4)          bs[nb++] = (const float*)d_in[i];
        // sz == 1 (is_casual) ignored
    }

    float *gQ, *gK, *gV, *gA;
    int *gidx, *gcnt;
    cudaGetSymbolAddress((void**)&gQ, g_Q);
    cudaGetSymbolAddress((void**)&gK, g_K);
    cudaGetSymbolAddress((void**)&gV, g_V);
    cudaGetSymbolAddress((void**)&gA, g_A);
    cudaGetSymbolAddress((void**)&gidx, g_idx);
    cudaGetSymbolAddress((void**)&gcnt, g_cnt);

    dim3 gGrid(DD / 128, MTOT / 128); // (8, 32)

    build_idx_kernel<<<BB, 1024>>>(masks[0], masks[1], gidx, gcnt);
    gemm_tn_kernel<<<gGrid, 256>>>(qkv[0], Ws[0], bs[0], gQ, nullptr, nullptr);
    gemm_tn_kernel<<<gGrid, 256>>>(qkv[1], Ws[1], bs[1], gK, gidx, gcnt);
    gemm_tn_kernel<<<gGrid, 256>>>(qkv[2], Ws[2], bs[2], gV, gidx, gcnt);
    attn_kernel<<<dim3(SS / 64, HH, BB), 256>>>(gQ, gK, gV, gA, gcnt);
    gemm_tn_kernel<<<gGrid, 256>>>(gA, Ws[3], bs[3], (float*)d_out, nullptr, nullptr);
}

// round 3
// speedup vs baseline: 1.0881x; 1.0881x over previous
#include <cuda_runtime.h>
#include <cstdint>
#include <cstddef>

// Problem constants
#define BB 2
#define SS 2048
#define DD 1024
#define HH 16
#define HDIM 64
#define MTOT (BB * SS) // 4096

// ---------------------------------------------------------------------------
// Scratch (device globals; allocation inside kernel_launch is forbidden)
// ---------------------------------------------------------------------------
__device__ float g_Q[(size_t)MTOT * DD];
__device__ float g_K[(size_t)MTOT * DD];
__device__ float g_V[(size_t)MTOT * DD];
__device__ float g_A[(size_t)MTOT * DD];
__device__ int   g_idx[MTOT];
__device__ int   g_cnt[BB];

// ---------------------------------------------------------------------------
// cp.async helpers
// ---------------------------------------------------------------------------
__device__ __forceinline__ void cp16(unsigned dst, const void* src) {
    asm volatile("cp.async.cg.shared.global [%0], [%1], 16;" :: "r"(dst), "l"(src));
}
__device__ __forceinline__ void cp_commit() {
    asm volatile("cp.async.commit_group;");
}
__device__ __forceinline__ void cp_wait0() {
    asm volatile("cp.async.wait_group 0;" ::: "memory");
}

// ---------------------------------------------------------------------------
// Kernel 1: deterministic mask compaction (prefix scan, no atomics)
// ---------------------------------------------------------------------------
__global__ __launch_bounds__(1024) void build_idx_kernel(
    const int* __restrict__ kp, const int* __restrict__ am,
    int* __restrict__ idx, int* __restrict__ counts)
{
    __shared__ int ssum[1024];
    const int b = blockIdx.x;
    const int t = threadIdx.x;
    const int base = b * SS;
    const int s0 = 2 * t, s1 = 2 * t + 1;
    int v0 = (kp[base + s0] == 0 && am[base + s0] == 0) ? 1 : 0;
    int v1 = (kp[base + s1] == 0 && am[base + s1] == 0) ? 1 : 0;
    ssum[t] = v0 + v1;
    __syncthreads();
    for (int off = 1; off < 1024; off <<= 1) {
        int add = (t >= off) ? ssum[t - off] : 0;
        int val = ssum[t];
        __syncthreads();
        ssum[t] = val + add;
        __syncthreads();
    }
    int excl = ssum[t] - (v0 + v1);
    if (v0) idx[base + excl]      = base + s0;
    if (v1) idx[base + excl + v0] = base + s1;
    if (t == 1023) counts[b] = ssum[1023];
}

// ---------------------------------------------------------------------------
// Kernel 2: SGEMM  C[m,n] = sum_k A[m,k] * W[n,k] + bias[n]
// Double-buffered smem (1 sync/slab), register fragment pipeline,
// thread cols split {4tx, 64+4tx} / rows {4ty, 64+4ty} (min bank conflicts).
// ---------------------------------------------------------------------------
__global__ __launch_bounds__(256, 2) void gemm_tn_kernel(
    const float* __restrict__ A, const float* __restrict__ W,
    const float* __restrict__ bias, float* __restrict__ C,
    const int* __restrict__ gather, const int* __restrict__ counts)
{
    __shared__ float As[2][8][132];
    __shared__ float Bs[2][8][132];
    const int nBase = blockIdx.x * 128;
    const int mBase = blockIdx.y * 128;
    if (gather) {
        int bb = mBase >> 11;
        if ((mBase & 2047) >= counts[bb]) return;
    }
    const int t  = threadIdx.x;
    const int tx = t & 15, ty = t >> 4;
    const int lRow = t >> 1;
    const int lC4  = (t & 1) * 4;

    int srcRow; bool rowOk = true;
    {
        int m = mBase + lRow;
        if (gather) {
            int bb = m >> 11, jj = m & 2047;
            rowOk = jj < counts[bb];
            srcRow = rowOk ? gather[m] : 0;
        } else {
            srcRow = m;
        }
    }
    const float* Aptr = A + (size_t)srcRow * DD + lC4;
    const float* Wptr = W + (size_t)(nBase + lRow) * DD + lC4;

    float acc[8][8];
#pragma unroll
    for (int i = 0; i < 8; i++)
#pragma unroll
        for (int j = 0; j < 8; j++) acc[i][j] = 0.f;

    float4 pa = rowOk ? *(const float4*)(Aptr) : make_float4(0.f, 0.f, 0.f, 0.f);
    float4 pw = *(const float4*)(Wptr);

    int buf = 0;
    for (int k0 = 0; k0 < DD; k0 += 8) {
        As[buf][lC4 + 0][lRow] = pa.x; As[buf][lC4 + 1][lRow] = pa.y;
        As[buf][lC4 + 2][lRow] = pa.z; As[buf][lC4 + 3][lRow] = pa.w;
        Bs[buf][lC4 + 0][lRow] = pw.x; Bs[buf][lC4 + 1][lRow] = pw.y;
        Bs[buf][lC4 + 2][lRow] = pw.z; Bs[buf][lC4 + 3][lRow] = pw.w;
        if (k0 + 8 < DD) {
            pa = rowOk ? *(const float4*)(Aptr + k0 + 8) : make_float4(0.f, 0.f, 0.f, 0.f);
            pw = *(const float4*)(Wptr + k0 + 8);
        }
        __syncthreads();

        float af[2][8], bf[2][8];
        {
            float4 x0 = *(const float4*)&As[buf][0][4 * ty];
            float4 x1 = *(const float4*)&As[buf][0][64 + 4 * ty];
            float4 y0 = *(const float4*)&Bs[buf][0][4 * tx];
            float4 y1 = *(const float4*)&Bs[buf][0][64 + 4 * tx];
            af[0][0] = x0.x; af[0][1] = x0.y; af[0][2] = x0.z; af[0][3] = x0.w;
            af[0][4] = x1.x; af[0][5] = x1.y; af[0][6] = x1.z; af[0][7] = x1.w;
            bf[0][0] = y0.x; bf[0][1] = y0.y; bf[0][2] = y0.z; bf[0][3] = y0.w;
            bf[0][4] = y1.x; bf[0][5] = y1.y; bf[0][6] = y1.z; bf[0][7] = y1.w;
        }
#pragma unroll
        for (int kk = 0; kk < 8; kk++) {
            const int cur = kk & 1, nxt = cur ^ 1;
            if (kk < 7) {
                float4 x0 = *(const float4*)&As[buf][kk + 1][4 * ty];
                float4 x1 = *(const float4*)&As[buf][kk + 1][64 + 4 * ty];
                float4 y0 = *(const float4*)&Bs[buf][kk + 1][4 * tx];
                float4 y1 = *(const float4*)&Bs[buf][kk + 1][64 + 4 * tx];
                af[nxt][0] = x0.x; af[nxt][1] = x0.y; af[nxt][2] = x0.z; af[nxt][3] = x0.w;
                af[nxt][4] = x1.x; af[nxt][5] = x1.y; af[nxt][6] = x1.z; af[nxt][7] = x1.w;
                bf[nxt][0] = y0.x; bf[nxt][1] = y0.y; bf[nxt][2] = y0.z; bf[nxt][3] = y0.w;
                bf[nxt][4] = y1.x; bf[nxt][5] = y1.y; bf[nxt][6] = y1.z; bf[nxt][7] = y1.w;
            }
#pragma unroll
            for (int i = 0; i < 8; i++)
#pragma unroll
                for (int j = 0; j < 8; j++)
                    acc[i][j] += af[cur][i] * bf[cur][j];
        }
        buf ^= 1;
    }

#pragma unroll
    for (int i = 0; i < 8; i++) {
        int rloc = (i < 4) ? (ty * 4 + i) : (64 + ty * 4 + i - 4);
        int m = mBase + rloc;
        bool ok = true;
        if (gather) ok = (m & 2047) < counts[m >> 11];
        if (ok) {
            float* cp = C + (size_t)m * DD + nBase;
            const float* bp = bias + nBase;
            *(float4*)(cp + 4 * tx) =
                make_float4(acc[i][0] + bp[4 * tx + 0], acc[i][1] + bp[4 * tx + 1],
                            acc[i][2] + bp[4 * tx + 2], acc[i][3] + bp[4 * tx + 3]);
            *(float4*)(cp + 64 + 4 * tx) =
                make_float4(acc[i][4] + bp[64 + 4 * tx + 0], acc[i][5] + bp[64 + 4 * tx + 1],
                            acc[i][6] + bp[64 + 4 * tx + 2], acc[i][7] + bp[64 + 4 * tx + 3]);
        }
    }
}

// ---------------------------------------------------------------------------
// Kernel 3: flash attention, cp.async double-buffered K/V tiles.
// Dynamic smem 96KB: Q[64x64] | K[2][64x64] | V[2][64x64] | P[64x64]
// ---------------------------------------------------------------------------
#define SM_Q 0
#define SM_K 4096
#define SM_V 12288
#define SM_P 20480
#define ATTN_SMEM_BYTES (24576 * 4)

__device__ __forceinline__ void stage_kv(unsigned sbase, const float* __restrict__ Kg,
                                         const float* __restrict__ Vg, int buf, int t)
{
    const unsigned kofs = (SM_K + buf * 4096) * 4u;
    const unsigned vofs = (SM_V + buf * 4096) * 4u;
#pragma unroll
    for (int it = 0; it < 4; it++) {
        int i = t + it * 256;
        int r = i >> 4, cq = i & 15;
        cp16(sbase + kofs + (r * 64 + 4 * (cq ^ ((r >> 2) & 7))) * 4u,
             Kg + (size_t)r * DD + 4 * cq);
        cp16(sbase + vofs + (r * 64 + 4 * cq) * 4u,
             Vg + (size_t)r * DD + 4 * cq);
    }
}

__global__ __launch_bounds__(256, 2) void attn_kernel(
    const float* __restrict__ Q, const float* __restrict__ K,
    const float* __restrict__ V, float* __restrict__ O,
    const int* __restrict__ counts)
{
    extern __shared__ float sm[];
    const unsigned sbase = (unsigned)__cvta_generic_to_shared(sm);

    const int qb = blockIdx.x, h = blockIdx.y, b = blockIdx.z;
    const int t  = threadIdx.x;
    const int tx = t & 15, ty = t >> 4;
    const int q0 = qb * 64;
    const int cnt = counts[b];
    const int nb = (cnt + 63) >> 6;

    // prologue: stage Q tile + k-block 0 (one cp.async group)
    const float* Qg = Q + (size_t)(b * SS + q0) * DD + h * HDIM;
#pragma unroll
    for (int it = 0; it < 4; it++) {
        int i = t + it * 256;
        int r = i >> 4, cq = i & 15;
        cp16(sbase + (SM_Q + r * 64 + 4 * cq) * 4u, Qg + (size_t)r * DD + 4 * cq);
    }
    stage_kv(sbase, K + (size_t)(b * SS) * DD + h * HDIM,
                    V + (size_t)(b * SS) * DD + h * HDIM, 0, t);
    cp_commit();

    float m_i[4], l_i[4], acc[4][4];
#pragma unroll
    for (int i = 0; i < 4; i++) {
        m_i[i] = -1e30f; l_i[i] = 0.f;
#pragma unroll
        for (int j = 0; j < 4; j++) acc[i][j] = 0.f;
    }

    int buf = 0;
    for (int kb = 0; kb < nb; kb++) {
        cp_wait0();
        __syncthreads(); // K/V[buf] ready; all warps done with previous iter

        if (kb + 1 < nb) { // prefetch next k-block into alt buffers
            const int kn = (kb + 1) * 64;
            stage_kv(sbase, K + (size_t)(b * SS + kn) * DD + h * HDIM,
                            V + (size_t)(b * SS + kn) * DD + h * HDIM, buf ^ 1, t);
            cp_commit();
        }

        const float* Qt = sm + SM_Q;
        const float* Kt = sm + SM_K + buf * 4096;

        float s[4][4];
#pragma unroll
        for (int i = 0; i < 4; i++)
#pragma unroll
            for (int j = 0; j < 4; j++) s[i][j] = 0.f;
#pragma unroll
        for (int d4 = 0; d4 < 16; d4++) {
            float4 qv[4];
#pragma unroll
            for (int i = 0; i < 4; i++)
                qv[i] = *(const float4*)&Qt[(ty * 4 + i) * 64 + 4 * d4];
#pragma unroll
            for (int j = 0; j < 4; j++) {
                float4 kv = *(const float4*)&Kt[(4 * tx + j) * 64 + 4 * (d4 ^ (tx & 7))];
#pragma unroll
                for (int i = 0; i < 4; i++)
                    s[i][j] += qv[i].x * kv.x + qv[i].y * kv.y +
                               qv[i].z * kv.z + qv[i].w * kv.w;
            }
        }

        const int kbase = kb * 64;
#pragma unroll
        for (int j = 0; j < 4; j++) {
            bool dead = (kbase + 4 * tx + j >= cnt);
#pragma unroll
            for (int i = 0; i < 4; i++)
                s[i][j] = dead ? -1e30f : s[i][j] * 0.125f;
        }

        // online softmax (16-lane reductions)
        float rmax[4], rsum[4];
#pragma unroll
        for (int i = 0; i < 4; i++) {
            rmax[i] = fmaxf(fmaxf(s[i][0], s[i][1]), fmaxf(s[i][2], s[i][3]));
        }
#pragma unroll
        for (int o = 1; o < 16; o <<= 1)
#pragma unroll
            for (int i = 0; i < 4; i++)
                rmax[i] = fmaxf(rmax[i], __shfl_xor_sync(0xffffffffu, rmax[i], o));
#pragma unroll
        for (int i = 0; i < 4; i++) {
            float mn = fmaxf(m_i[i], rmax[i]);
            float corr = __expf(m_i[i] - mn);
            m_i[i] = mn;
            float rs = 0.f;
#pragma unroll
            for (int j = 0; j < 4; j++) {
                float p = __expf(s[i][j] - mn);
                s[i][j] = p;
                rs += p;
            }
            rsum[i] = rs;
            l_i[i] *= corr;
#pragma unroll
            for (int j = 0; j < 4; j++) acc[i][j] *= corr;
        }
#pragma unroll
        for (int o = 1; o < 16; o <<= 1)
#pragma unroll
            for (int i = 0; i < 4; i++)
                rsum[i] += __shfl_xor_sync(0xffffffffu, rsum[i], o);
#pragma unroll
        for (int i = 0; i < 4; i++) l_i[i] += rsum[i];

        // write P tile (separate buffer — no hazard with K)
        float* Ps = sm + SM_P;
#pragma unroll
        for (int i = 0; i < 4; i++)
            *(float4*)&Ps[(ty * 4 + i) * 64 + 4 * tx] =
                make_float4(s[i][0], s[i][1], s[i][2], s[i][3]);
        __syncthreads();

        // O += P V
        const float* Vt = sm + SM_V + buf * 4096;
#pragma unroll 8
        for (int k = 0; k < 64; k++) {
            float4 vv = *(const float4*)&Vt[k * 64 + 4 * tx];
#pragma unroll
            for (int i = 0; i < 4; i++) {
                float p = Ps[(ty * 4 + i) * 64 + k];
                acc[i][0] += p * vv.x; acc[i][1] += p * vv.y;
                acc[i][2] += p * vv.z; acc[i][3] += p * vv.w;
            }
        }
        buf ^= 1;
    }

#pragma unroll
    for (int i = 0; i < 4; i++) {
        float inv = 1.0f / l_i[i];
        int row = b * SS + q0 + ty * 4 + i;
        *(float4*)&O[(size_t)row * DD + h * HDIM + 4 * tx] =
            make_float4(acc[i][0] * inv, acc[i][1] * inv,
                        acc[i][2] * inv, acc[i][3] * inv);
    }
}

// ---------------------------------------------------------------------------
// Launch — inputs classified by element count
// ---------------------------------------------------------------------------
extern "C" void kernel_launch(void* const* d_in, const int* in_sizes, int n_in,
                              void* d_out, int out_size)
{
    (void)out_size;
    const float* qkv[3]   = {nullptr, nullptr, nullptr};
    const int*   masks[2] = {nullptr, nullptr};
    const float* Ws[4]    = {nullptr, nullptr, nullptr, nullptr};
    const float* bs[4]    = {nullptr, nullptr, nullptr, nullptr};
    int nqkv = 0, nmask = 0, nW = 0, nb = 0;
    for (int i = 0; i < n_in; i++) {
        int sz = in_sizes[i];
        if (sz == MTOT * DD && nqkv < 3)      qkv[nqkv++] = (const float*)d_in[i];
        else if (sz == MTOT && nmask < 2)     masks[nmask++] = (const int*)d_in[i];
        else if (sz == DD * DD && nW < 4)     Ws[nW++] = (const float*)d_in[i];
        else if (sz == DD && nb < 4)          bs[nb++] = (const float*)d_in[i];
    }

    static int attr_done = 0;
    if (!attr_done) {
        cudaFuncSetAttribute(attn_kernel,
                             cudaFuncAttributeMaxDynamicSharedMemorySize,
                             ATTN_SMEM_BYTES);
        attr_done = 1;
    }

    float *gQ, *gK, *gV, *gA;
    int *gidx, *gcnt;
    cudaGetSymbolAddress((void**)&gQ, g_Q);
    cudaGetSymbolAddress((void**)&gK, g_K);
    cudaGetSymbolAddress((void**)&gV, g_V);
    cudaGetSymbolAddress((void**)&gA, g_A);
    cudaGetSymbolAddress((void**)&gidx, g_idx);
    cudaGetSymbolAddress((void**)&gcnt, g_cnt);

    dim3 gGrid(DD / 128, MTOT / 128); // (8, 32)

    build_idx_kernel<<<BB, 1024>>>(masks[0], masks[1], gidx, gcnt);
    gemm_tn_kernel<<<gGrid, 256>>>(qkv[0], Ws[0], bs[0], gQ, nullptr, nullptr);
    gemm_tn_kernel<<<gGrid, 256>>>(qkv[1], Ws[1], bs[1], gK, gidx, gcnt);
    gemm_tn_kernel<<<gGrid, 256>>>(qkv[2], Ws[2], bs[2], gV, gidx, gcnt);
    attn_kernel<<<dim3(SS / 64, HH, BB), 256, ATTN_SMEM_BYTES>>>(gQ, gK, gV, gA, gcnt);
    gemm_tn_kernel<<<gGrid, 256>>>(gA, Ws[3], bs[3], (float*)d_out, nullptr, nullptr);
}

// round 5
// speedup vs baseline: 1.9841x; 1.8234x over previous
#include <cuda_runtime.h>
#include <cuda_bf16.h>
#include <cstdint>
#include <cstddef>

// Problem constants
#define BB 2
#define SS 2048
#define DD 1024
#define HH 16
#define HDIM 64
#define MTOT (BB * SS) // 4096

// ---------------------------------------------------------------------------
// Scratch (device globals)
// ---------------------------------------------------------------------------
__device__ float g_Q[(size_t)MTOT * DD];
__device__ float g_K[(size_t)MTOT * DD];
__device__ float g_V[(size_t)MTOT * DD];
__device__ float g_A[(size_t)MTOT * DD];
__device__ int   g_idx[MTOT];
__device__ int   g_cnt[BB];
// bf16 hi/lo splits
__device__ __nv_bfloat16 g_qh[(size_t)MTOT * DD], g_ql[(size_t)MTOT * DD];
__device__ __nv_bfloat16 g_kh[(size_t)MTOT * DD], g_kl[(size_t)MTOT * DD];
__device__ __nv_bfloat16 g_vh[(size_t)MTOT * DD], g_vl[(size_t)MTOT * DD];
__device__ __nv_bfloat16 g_ah[(size_t)MTOT * DD], g_al[(size_t)MTOT * DD];
__device__ __nv_bfloat16 g_Wh[4][(size_t)DD * DD], g_Wl[4][(size_t)DD * DD];

// ---------------------------------------------------------------------------
// PTX helpers (base sm_103 ISA only: cp.async, ldmatrix, mma.sync)
// ---------------------------------------------------------------------------
__device__ __forceinline__ void cp16(unsigned dst, const void* src) {
    asm volatile("cp.async.cg.shared.global [%0], [%1], 16;" :: "r"(dst), "l"(src));
}
__device__ __forceinline__ void cp_commit() { asm volatile("cp.async.commit_group;"); }
__device__ __forceinline__ void cp_wait0()  { asm volatile("cp.async.wait_group 0;" ::: "memory"); }

__device__ __forceinline__ void ldmx4(uint32_t* r, uint32_t addr) {
    asm volatile("ldmatrix.sync.aligned.m8n8.x4.shared.b16 {%0,%1,%2,%3}, [%4];"
                 : "=r"(r[0]), "=r"(r[1]), "=r"(r[2]), "=r"(r[3]) : "r"(addr));
}
__device__ __forceinline__ void mma_bf16(float* d, const uint32_t* a, const uint32_t* b) {
    asm volatile(
        "mma.sync.aligned.m16n8k16.row.col.f32.bf16.bf16.f32 "
        "{%0,%1,%2,%3}, {%4,%5,%6,%7}, {%8,%9}, {%0,%1,%2,%3};"
        : "+f"(d[0]), "+f"(d[1]), "+f"(d[2]), "+f"(d[3])
        : "r"(a[0]), "r"(a[1]), "r"(a[2]), "r"(a[3]), "r"(b[0]), "r"(b[1]));
}

// ---------------------------------------------------------------------------
// Kernel: fp32 -> bf16 (hi, lo) split, 4 elements/thread
// ---------------------------------------------------------------------------
__global__ __launch_bounds__(256) void conv_split_kernel(
    const float* __restrict__ x, __nv_bfloat16* __restrict__ hi,
    __nv_bfloat16* __restrict__ lo, int n4)
{
    int i = blockIdx.x * blockDim.x + threadIdx.x;
    if (i >= n4) return;
    float4 v = ((const float4*)x)[i];
    __nv_bfloat16 h0 = __float2bfloat16(v.x), h1 = __float2bfloat16(v.y);
    __nv_bfloat16 h2 = __float2bfloat16(v.z), h3 = __float2bfloat16(v.w);
    __nv_bfloat16 l0 = __float2bfloat16(v.x - __bfloat162float(h0));
    __nv_bfloat16 l1 = __float2bfloat16(v.y - __bfloat162float(h1));
    __nv_bfloat16 l2 = __float2bfloat16(v.z - __bfloat162float(h2));
    __nv_bfloat16 l3 = __float2bfloat16(v.w - __bfloat162float(h3));
    ((__nv_bfloat162*)hi)[2 * i]     = __nv_bfloat162(h0, h1);
    ((__nv_bfloat162*)hi)[2 * i + 1] = __nv_bfloat162(h2, h3);
    ((__nv_bfloat162*)lo)[2 * i]     = __nv_bfloat162(l0, l1);
    ((__nv_bfloat162*)lo)[2 * i + 1] = __nv_bfloat162(l2, l3);
}

// ---------------------------------------------------------------------------
// Kernel 1: deterministic mask compaction
// ---------------------------------------------------------------------------
__global__ __launch_bounds__(1024) void build_idx_kernel(
    const int* __restrict__ kp, const int* __restrict__ am,
    int* __restrict__ idx, int* __restrict__ counts)
{
    __shared__ int ssum[1024];
    const int b = blockIdx.x;
    const int t = threadIdx.x;
    const int base = b * SS;
    const int s0 = 2 * t, s1 = 2 * t + 1;
    int v0 = (kp[base + s0] == 0 && am[base + s0] == 0) ? 1 : 0;
    int v1 = (kp[base + s1] == 0 && am[base + s1] == 0) ? 1 : 0;
    ssum[t] = v0 + v1;
    __syncthreads();
    for (int off = 1; off < 1024; off <<= 1) {
        int add = (t >= off) ? ssum[t - off] : 0;
        int val = ssum[t];
        __syncthreads();
        ssum[t] = val + add;
        __syncthreads();
    }
    int excl = ssum[t] - (v0 + v1);
    if (v0) idx[base + excl]      = base + s0;
    if (v1) idx[base + excl + v0] = base + s1;
    if (t == 1023) counts[b] = ssum[1023];
}

// ---------------------------------------------------------------------------
// Kernel 2: HMMA (mma.sync bf16) GEMM  C[m,n] = sum_k A[m,k]*W[n,k] + bias[n]
// hi/lo split: C = Ahi*Bhi + Ahi*Blo + Alo*Bhi (fp32 accum).
// Block 128x128, BK=64, 8 warps (warp tile 32x64), cp.async double buffer.
// SMEM per stage: Ahi 16K | Alo 16K | Bhi 16K | Blo 16K = 64KB; x2 = 128KB.
// Tiles are [128 rows][64 bf16] = rows of 128B, SW128 XOR swizzle on 16B units.
// ---------------------------------------------------------------------------
#define GSTAGE 65536
#define GSM_BYTES (2 * GSTAGE)

__global__ __launch_bounds__(256, 1) void gemm_mma_kernel(
    const __nv_bfloat16* __restrict__ Ahi, const __nv_bfloat16* __restrict__ Alo,
    const __nv_bfloat16* __restrict__ Bhi, const __nv_bfloat16* __restrict__ Blo,
    const float* __restrict__ bias, float* __restrict__ C,
    const int* __restrict__ gather, const int* __restrict__ counts)
{
    extern __shared__ char smem[];
    const uint32_t sb = (uint32_t)__cvta_generic_to_shared(smem);
    const int nBase = blockIdx.x * 128;
    const int mBase = blockIdx.y * 128;
    int cnt = 0;
    if (gather) {
        cnt = counts[mBase >> 11];
        if ((mBase & 2047) >= cnt) return; // whole block invalid
    }
    const int t    = threadIdx.x;
    const int wid  = t >> 5;
    const int lane = t & 31;
    const int wm   = wid >> 1;   // 0..3 -> m offset wm*32
    const int wn   = wid & 1;    // 0..1 -> n offset wn*64

    // ---- staging setup: thread t stages row (t>>1), 16B units uBase..uBase+3
    const int sRow  = t >> 1;
    const int uBase = (t & 1) * 4;
    int srcRow; // A source row (gather-aware)
    {
        int m = mBase + sRow;
        if (gather) {
            bool ok = (m & 2047) < cnt;
            srcRow = ok ? gather[m] : ((m >> 11) * SS); // safe dummy row
        } else {
            srcRow = m;
        }
    }
    const __nv_bfloat16* aHp = Ahi + (size_t)srcRow * DD;
    const __nv_bfloat16* aLp = Alo + (size_t)srcRow * DD;
    const __nv_bfloat16* bHp = Bhi + (size_t)(nBase + sRow) * DD;
    const __nv_bfloat16* bLp = Blo + (size_t)(nBase + sRow) * DD;
    // swizzled byte offsets for the 4 units this thread stores
    uint32_t stOff[4];
#pragma unroll
    for (int i = 0; i < 4; i++)
        stOff[i] = sRow * 128 + (((uBase + i) ^ (sRow & 7)) << 4);

    // ---- ldmatrix lane address bases
    // A fragment (m16xk16) x4 matrix order: a0(m0-7,k0-7) a1(m8-15,k0-7)
    //                                       a2(m0-7,k8-15) a3(m8-15,k8-15)
    //   lane group g = lane>>3: row += (g&1)*8, unit += (g>>1)
    // B fragment (n8xk16 from row-major [n][k]) pair-load x4 order:
    //   m0: tile j   rows, k0-7   m1: tile j   rows, k8-15
    //   m2: tile j+1 rows, k0-7   m3: tile j+1 rows, k8-15
    //   lane group g: row += (g>>1)*8, unit += (g&1)
    const int g  = lane >> 3;
    const int lr = lane & 7;
    const uint32_t rowA = wm * 32 + (g & 1) * 8 + lr;   // + mt*16
    const uint32_t rxa  = rowA & 7;                     // invariant under +16
    const uint32_t aoff = rowA * 128;
    const int aU = g >> 1;
    const uint32_t rowB = wn * 64 + (g >> 1) * 8 + lr;  // + jp*16
    const uint32_t rxb  = rowB & 7;
    const uint32_t boff = rowB * 128;
    const int bU = g & 1;

    float acc[2][8][4];
#pragma unroll
    for (int mt = 0; mt < 2; mt++)
#pragma unroll
        for (int j = 0; j < 8; j++)
#pragma unroll
            for (int r = 0; r < 4; r++) acc[mt][j][r] = 0.f;

    // ---- stage chunk 0
    {
        const uint32_t s0 = sb;
#pragma unroll
        for (int i = 0; i < 4; i++) {
            int kk = (uBase + i) * 8;
            cp16(s0 +         stOff[i], aHp + kk);
            cp16(s0 + 16384 + stOff[i], aLp + kk);
            cp16(s0 + 32768 + stOff[i], bHp + kk);
            cp16(s0 + 49152 + stOff[i], bLp + kk);
        }
        cp_commit();
    }

    for (int c = 0; c < 16; c++) {
        cp_wait0();
        __syncthreads();
        if (c + 1 < 16) { // prefetch next chunk
            const uint32_t sN = sb + ((c + 1) & 1) * GSTAGE;
            const int k0 = (c + 1) * 64;
#pragma unroll
            for (int i = 0; i < 4; i++) {
                int kk = k0 + (uBase + i) * 8;
                cp16(sN +         stOff[i], aHp + kk);
                cp16(sN + 16384 + stOff[i], aLp + kk);
                cp16(sN + 32768 + stOff[i], bHp + kk);
                cp16(sN + 49152 + stOff[i], bLp + kk);
            }
            cp_commit();
        }

        const uint32_t base = sb + (c & 1) * GSTAGE;
        const uint32_t tAh = base, tAl = base + 16384;
        const uint32_t tBh = base + 32768, tBl = base + 49152;

#pragma unroll
        for (int ks = 0; ks < 4; ks++) {
            uint32_t ah[2][4], al[2][4];
#pragma unroll
            for (int mt = 0; mt < 2; mt++) {
                uint32_t sw = (((2 * ks + aU) ^ rxa) << 4);
                ldmx4(ah[mt], tAh + aoff + mt * 2048 + sw);
                ldmx4(al[mt], tAl + aoff + mt * 2048 + sw);
            }
            uint32_t bh[8][2], bl[8][2];
#pragma unroll
            for (int jp = 0; jp < 4; jp++) {
                uint32_t sw = (((2 * ks + bU) ^ rxb) << 4);
                uint32_t r4[4];
                ldmx4(r4, tBh + boff + jp * 2048 + sw);
                bh[2 * jp][0] = r4[0]; bh[2 * jp][1] = r4[1];
                bh[2 * jp + 1][0] = r4[2]; bh[2 * jp + 1][1] = r4[3];
                ldmx4(r4, tBl + boff + jp * 2048 + sw);
                bl[2 * jp][0] = r4[0]; bl[2 * jp][1] = r4[1];
                bl[2 * jp + 1][0] = r4[2]; bl[2 * jp + 1][1] = r4[3];
            }
#pragma unroll
            for (int mt = 0; mt < 2; mt++)
#pragma unroll
                for (int j = 0; j < 8; j++) {
                    mma_bf16(acc[mt][j], ah[mt], bh[j]);
                    mma_bf16(acc[mt][j], ah[mt], bl[j]);
                    mma_bf16(acc[mt][j], al[mt], bh[j]);
                }
        }
        __syncthreads();
    }

    // ---- epilogue: acc lane layout: c0,c1 -> (m = lane>>2, n = 2*(lane&3)+{0,1})
    //                                 c2,c3 -> (m+8, same n)
#pragma unroll
    for (int mt = 0; mt < 2; mt++) {
        int m0 = mBase + wm * 32 + mt * 16 + (lane >> 2);
        int m1 = m0 + 8;
        bool ok0 = true, ok1 = true;
        if (gather) {
            ok0 = (m0 & 2047) < cnt;
            ok1 = (m1 & 2047) < cnt;
        }
#pragma unroll
        for (int j = 0; j < 8; j++) {
            int n = nBase + wn * 64 + j * 8 + 2 * (lane & 3);
            float b0v = bias[n], b1v = bias[n + 1];
            if (ok0)
                *(float2*)&C[(size_t)m0 * DD + n] =
                    make_float2(acc[mt][j][0] + b0v, acc[mt][j][1] + b1v);
            if (ok1)
                *(float2*)&C[(size_t)m1 * DD + n] =
                    make_float2(acc[mt][j][2] + b0v, acc[mt][j][3] + b1v);
        }
    }
}

// ---------------------------------------------------------------------------
// Kernel 3: flash attention, cp.async double-buffered K/V tiles.
// Dynamic smem 96KB: Q[64x64] | K[2][64x64] | V[2][64x64] | P[64x64]
// ---------------------------------------------------------------------------
#define SM_Q 0
#define SM_K 4096
#define SM_V 12288
#define SM_P 20480
#define ATTN_SMEM_BYTES (24576 * 4)

__device__ __forceinline__ void stage_kv(unsigned sbase, const float* __restrict__ Kg,
                                         const float* __restrict__ Vg, int buf, int t)
{
    const unsigned kofs = (SM_K + buf * 4096) * 4u;
    const unsigned vofs = (SM_V + buf * 4096) * 4u;
#pragma unroll
    for (int it = 0; it < 4; it++) {
        int i = t + it * 256;
        int r = i >> 4, cq = i & 15;
        cp16(sbase + kofs + (r * 64 + 4 * (cq ^ ((r >> 2) & 7))) * 4u,
             Kg + (size_t)r * DD + 4 * cq);
        cp16(sbase + vofs + (r * 64 + 4 * cq) * 4u,
             Vg + (size_t)r * DD + 4 * cq);
    }
}

__global__ __launch_bounds__(256, 2) void attn_kernel(
    const float* __restrict__ Q, const float* __restrict__ K,
    const float* __restrict__ V, float* __restrict__ O,
    const int* __restrict__ counts)
{
    extern __shared__ float sm[];
    const unsigned sbase = (unsigned)__cvta_generic_to_shared(sm);

    const int qb = blockIdx.x, h = blockIdx.y, b = blockIdx.z;
    const int t  = threadIdx.x;
    const int tx = t & 15, ty = t >> 4;
    const int q0 = qb * 64;
    const int cnt = counts[b];
    const int nb = (cnt + 63) >> 6;

    const float* Qg = Q + (size_t)(b * SS + q0) * DD + h * HDIM;
#pragma unroll
    for (int it = 0; it < 4; it++) {
        int i = t + it * 256;
        int r = i >> 4, cq = i & 15;
        cp16(sbase + (SM_Q + r * 64 + 4 * cq) * 4u, Qg + (size_t)r * DD + 4 * cq);
    }
    stage_kv(sbase, K + (size_t)(b * SS) * DD + h * HDIM,
                    V + (size_t)(b * SS) * DD + h * HDIM, 0, t);
    cp_commit();

    float m_i[4], l_i[4], acc[4][4];
#pragma unroll
    for (int i = 0; i < 4; i++) {
        m_i[i] = -1e30f; l_i[i] = 0.f;
#pragma unroll
        for (int j = 0; j < 4; j++) acc[i][j] = 0.f;
    }

    int buf = 0;
    for (int kb = 0; kb < nb; kb++) {
        cp_wait0();
        __syncthreads();

        if (kb + 1 < nb) {
            const int kn = (kb + 1) * 64;
            stage_kv(sbase, K + (size_t)(b * SS + kn) * DD + h * HDIM,
                            V + (size_t)(b * SS + kn) * DD + h * HDIM, buf ^ 1, t);
            cp_commit();
        }

        const float* Qt = sm + SM_Q;
        const float* Kt = sm + SM_K + buf * 4096;

        float s[4][4];
#pragma unroll
        for (int i = 0; i < 4; i++)
#pragma unroll
            for (int j = 0; j < 4; j++) s[i][j] = 0.f;
#pragma unroll
        for (int d4 = 0; d4 < 16; d4++) {
            float4 qv[4];
#pragma unroll
            for (int i = 0; i < 4; i++)
                qv[i] = *(const float4*)&Qt[(ty * 4 + i) * 64 + 4 * d4];
#pragma unroll
            for (int j = 0; j < 4; j++) {
                float4 kv = *(const float4*)&Kt[(4 * tx + j) * 64 + 4 * (d4 ^ (tx & 7))];
#pragma unroll
                for (int i = 0; i < 4; i++)
                    s[i][j] += qv[i].x * kv.x + qv[i].y * kv.y +
                               qv[i].z * kv.z + qv[i].w * kv.w;
            }
        }

        const int kbase = kb * 64;
#pragma unroll
        for (int j = 0; j < 4; j++) {
            bool dead = (kbase + 4 * tx + j >= cnt);
#pragma unroll
            for (int i = 0; i < 4; i++)
                s[i][j] = dead ? -1e30f : s[i][j] * 0.125f;
        }

        float rmax[4], rsum[4];
#pragma unroll
        for (int i = 0; i < 4; i++)
            rmax[i] = fmaxf(fmaxf(s[i][0], s[i][1]), fmaxf(s[i][2], s[i][3]));
#pragma unroll
        for (int o = 1; o < 16; o <<= 1)
#pragma unroll
            for (int i = 0; i < 4; i++)
                rmax[i] = fmaxf(rmax[i], __shfl_xor_sync(0xffffffffu, rmax[i], o));
#pragma unroll
        for (int i = 0; i < 4; i++) {
            float mn = fmaxf(m_i[i], rmax[i]);
            float corr = __expf(m_i[i] - mn);
            m_i[i] = mn;
            float rs = 0.f;
#pragma unroll
            for (int j = 0; j < 4; j++) {
                float p = __expf(s[i][j] - mn);
                s[i][j] = p;
                rs += p;
            }
            rsum[i] = rs;
            l_i[i] *= corr;
#pragma unroll
            for (int j = 0; j < 4; j++) acc[i][j] *= corr;
        }
#pragma unroll
        for (int o = 1; o < 16; o <<= 1)
#pragma unroll
            for (int i = 0; i < 4; i++)
                rsum[i] += __shfl_xor_sync(0xffffffffu, rsum[i], o);
#pragma unroll
        for (int i = 0; i < 4; i++) l_i[i] += rsum[i];

        float* Ps = sm + SM_P;
#pragma unroll
        for (int i = 0; i < 4; i++)
            *(float4*)&Ps[(ty * 4 + i) * 64 + 4 * tx] =
                make_float4(s[i][0], s[i][1], s[i][2], s[i][3]);
        __syncthreads();

        // O += P V  (P read as float4 over k)
        const float* Vt = sm + SM_V + buf * 4096;
#pragma unroll 4
        for (int k4 = 0; k4 < 16; k4++) {
            float4 vv0 = *(const float4*)&Vt[(4 * k4 + 0) * 64 + 4 * tx];
            float4 vv1 = *(const float4*)&Vt[(4 * k4 + 1) * 64 + 4 * tx];
            float4 vv2 = *(const float4*)&Vt[(4 * k4 + 2) * 64 + 4 * tx];
            float4 vv3 = *(const float4*)&Vt[(4 * k4 + 3) * 64 + 4 * tx];
#pragma unroll
            for (int i = 0; i < 4; i++) {
                float4 pv = *(const float4*)&Ps[(ty * 4 + i) * 64 + 4 * k4];
                acc[i][0] += pv.x * vv0.x + pv.y * vv1.x + pv.z * vv2.x + pv.w * vv3.x;
                acc[i][1] += pv.x * vv0.y + pv.y * vv1.y + pv.z * vv2.y + pv.w * vv3.y;
                acc[i][2] += pv.x * vv0.z + pv.y * vv1.z + pv.z * vv2.z + pv.w * vv3.z;
                acc[i][3] += pv.x * vv0.w + pv.y * vv1.w + pv.z * vv2.w + pv.w * vv3.w;
            }
        }
        buf ^= 1;
    }

#pragma unroll
    for (int i = 0; i < 4; i++) {
        float inv = 1.0f / l_i[i];
        int row = b * SS + q0 + ty * 4 + i;
        *(float4*)&O[(size_t)row * DD + h * HDIM + 4 * tx] =
            make_float4(acc[i][0] * inv, acc[i][1] * inv,
                        acc[i][2] * inv, acc[i][3] * inv);
    }
}

// ---------------------------------------------------------------------------
// Launch
// ---------------------------------------------------------------------------
extern "C" void kernel_launch(void* const* d_in, const int* in_sizes, int n_in,
                              void* d_out, int out_size)
{
    (void)out_size;
    const float* qkv[3]   = {nullptr, nullptr, nullptr};
    const int*   masks[2] = {nullptr, nullptr};
    const float* Ws[4]    = {nullptr, nullptr, nullptr, nullptr};
    const float* bs[4]    = {nullptr, nullptr, nullptr, nullptr};
    int nqkv = 0, nmask = 0, nW = 0, nb = 0;
    for (int i = 0; i < n_in; i++) {
        int sz = in_sizes[i];
        if (sz == MTOT * DD && nqkv < 3)      qkv[nqkv++] = (const float*)d_in[i];
        else if (sz == MTOT && nmask < 2)     masks[nmask++] = (const int*)d_in[i];
        else if (sz == DD * DD && nW < 4)     Ws[nW++] = (const float*)d_in[i];
        else if (sz == DD && nb < 4)          bs[nb++] = (const float*)d_in[i];
    }

    static int attr_done = 0;
    if (!attr_done) {
        cudaFuncSetAttribute(attn_kernel,
                             cudaFuncAttributeMaxDynamicSharedMemorySize, ATTN_SMEM_BYTES);
        cudaFuncSetAttribute(gemm_mma_kernel,
                             cudaFuncAttributeMaxDynamicSharedMemorySize, GSM_BYTES);
        attr_done = 1;
    }

    float *gQ, *gK, *gV, *gA;
    int *gidx, *gcnt;
    __nv_bfloat16 *qh, *ql, *kh, *kl, *vh, *vl, *ah, *al, *wh, *wl;
    cudaGetSymbolAddress((void**)&gQ, g_Q);
    cudaGetSymbolAddress((void**)&gK, g_K);
    cudaGetSymbolAddress((void**)&gV, g_V);
    cudaGetSymbolAddress((void**)&gA, g_A);
    cudaGetSymbolAddress((void**)&gidx, g_idx);
    cudaGetSymbolAddress((void**)&gcnt, g_cnt);
    cudaGetSymbolAddress((void**)&qh, g_qh); cudaGetSymbolAddress((void**)&ql, g_ql);
    cudaGetSymbolAddress((void**)&kh, g_kh); cudaGetSymbolAddress((void**)&kl, g_kl);
    cudaGetSymbolAddress((void**)&vh, g_vh); cudaGetSymbolAddress((void**)&vl, g_vl);
    cudaGetSymbolAddress((void**)&ah, g_ah); cudaGetSymbolAddress((void**)&al, g_al);
    cudaGetSymbolAddress((void**)&wh, g_Wh); cudaGetSymbolAddress((void**)&wl, g_Wl);

    const int N4_ACT = MTOT * DD / 4;   // 1048576
    const int N4_W   = DD * DD / 4;     // 262144
    dim3 mmaGrid(DD / 128, MTOT / 128); // (8, 32)

    build_idx_kernel<<<BB, 1024>>>(masks[0], masks[1], gidx, gcnt);

    // split conversions
    conv_split_kernel<<<(N4_ACT + 255) / 256, 256>>>(qkv[0], qh, ql, N4_ACT);
    conv_split_kernel<<<(N4_ACT + 255) / 256, 256>>>(qkv[1], kh, kl, N4_ACT);
    conv_split_kernel<<<(N4_ACT + 255) / 256, 256>>>(qkv[2], vh, vl, N4_ACT);
    for (int w = 0; w < 4; w++)
        conv_split_kernel<<<(N4_W + 255) / 256, 256>>>(
            Ws[w], wh + (size_t)w * DD * DD, wl + (size_t)w * DD * DD, N4_W);

    // projections (HMMA tensor cores)
    gemm_mma_kernel<<<mmaGrid, 256, GSM_BYTES>>>(qh, ql, wh, wl, bs[0], gQ, nullptr, nullptr);
    gemm_mma_kernel<<<mmaGrid, 256, GSM_BYTES>>>(kh, kl, wh + (size_t)1 * DD * DD,
                                                 wl + (size_t)1 * DD * DD, bs[1], gK, gidx, gcnt);
    gemm_mma_kernel<<<mmaGrid, 256, GSM_BYTES>>>(vh, vl, wh + (size_t)2 * DD * DD,
                                                 wl + (size_t)2 * DD * DD, bs[2], gV, gidx, gcnt);

    attn_kernel<<<dim3(SS / 64, HH, BB), 256, ATTN_SMEM_BYTES>>>(gQ, gK, gV, gA, gcnt);

    // output projection
    conv_split_kernel<<<(N4_ACT + 255) / 256, 256>>>(gA, ah, al, N4_ACT);
    gemm_mma_kernel<<<mmaGrid, 256, GSM_BYTES>>>(ah, al, wh + (size_t)3 * DD * DD,
                                                 wl + (size_t)3 * DD * DD, bs[3],
                                                 (float*)d_out, nullptr, nullptr);
}

// round 6
// speedup vs baseline: 2.7080x; 1.3649x over previous
#include <cuda_runtime.h>
#include <cuda_bf16.h>
#include <cstdint>
#include <cstddef>

// Problem constants
#define BB 2
#define SS 2048
#define DD 1024
#define HH 16
#define HDIM 64
#define MTOT (BB * SS) // 4096

// ---------------------------------------------------------------------------
// Scratch (device globals; zero-initialized at module load)
// ---------------------------------------------------------------------------
__device__ int g_idx[MTOT];
__device__ int g_cnt[BB];
// bf16 hi/lo: raw inputs
__device__ __nv_bfloat16 g_qh[(size_t)MTOT * DD], g_ql[(size_t)MTOT * DD];
__device__ __nv_bfloat16 g_kh[(size_t)MTOT * DD], g_kl[(size_t)MTOT * DD];
__device__ __nv_bfloat16 g_vh[(size_t)MTOT * DD], g_vl[(size_t)MTOT * DD];
// weights
__device__ __nv_bfloat16 g_Wh[4][(size_t)DD * DD], g_Wl[4][(size_t)DD * DD];
// projected activations (bf16 hi/lo; K/V compacted per batch)
__device__ __nv_bfloat16 g_pqh[(size_t)MTOT * DD], g_pql[(size_t)MTOT * DD];
__device__ __nv_bfloat16 g_pkh[(size_t)MTOT * DD], g_pkl[(size_t)MTOT * DD];
__device__ __nv_bfloat16 g_pvh[(size_t)MTOT * DD], g_pvl[(size_t)MTOT * DD];
// attention output (bf16 hi/lo), input to Wo GEMM
__device__ __nv_bfloat16 g_ah[(size_t)MTOT * DD], g_al[(size_t)MTOT * DD];

// ---------------------------------------------------------------------------
// PTX helpers (base sm_103 ISA: cp.async, ldmatrix, mma.sync)
// ---------------------------------------------------------------------------
__device__ __forceinline__ void cp16(unsigned dst, const void* src) {
    asm volatile("cp.async.cg.shared.global [%0], [%1], 16;" :: "r"(dst), "l"(src));
}
__device__ __forceinline__ void cp_commit() { asm volatile("cp.async.commit_group;"); }
__device__ __forceinline__ void cp_wait0()  { asm volatile("cp.async.wait_group 0;" ::: "memory"); }

__device__ __forceinline__ void ldmx4(uint32_t* r, uint32_t addr) {
    asm volatile("ldmatrix.sync.aligned.m8n8.x4.shared.b16 {%0,%1,%2,%3}, [%4];"
                 : "=r"(r[0]), "=r"(r[1]), "=r"(r[2]), "=r"(r[3]) : "r"(addr));
}
__device__ __forceinline__ void ldmx4t(uint32_t* r, uint32_t addr) {
    asm volatile("ldmatrix.sync.aligned.m8n8.x4.trans.shared.b16 {%0,%1,%2,%3}, [%4];"
                 : "=r"(r[0]), "=r"(r[1]), "=r"(r[2]), "=r"(r[3]) : "r"(addr));
}
__device__ __forceinline__ void mma_bf16(float* d, const uint32_t* a, const uint32_t* b) {
    asm volatile(
        "mma.sync.aligned.m16n8k16.row.col.f32.bf16.bf16.f32 "
        "{%0,%1,%2,%3}, {%4,%5,%6,%7}, {%8,%9}, {%0,%1,%2,%3};"
        : "+f"(d[0]), "+f"(d[1]), "+f"(d[2]), "+f"(d[3])
        : "r"(a[0]), "r"(a[1]), "r"(a[2]), "r"(a[3]), "r"(b[0]), "r"(b[1]));
}
__device__ __forceinline__ uint32_t pack_bf16(float a, float b) {
    __nv_bfloat162 v(__float2bfloat16(a), __float2bfloat16(b));
    return *(uint32_t*)&v;
}

// ---------------------------------------------------------------------------
// Kernel: fp32 -> bf16 (hi, lo) split, 4 elements/thread
// ---------------------------------------------------------------------------
__global__ __launch_bounds__(256) void conv_split_kernel(
    const float* __restrict__ x, __nv_bfloat16* __restrict__ hi,
    __nv_bfloat16* __restrict__ lo, int n4)
{
    int i = blockIdx.x * blockDim.x + threadIdx.x;
    if (i >= n4) return;
    float4 v = ((const float4*)x)[i];
    __nv_bfloat16 h0 = __float2bfloat16(v.x), h1 = __float2bfloat16(v.y);
    __nv_bfloat16 h2 = __float2bfloat16(v.z), h3 = __float2bfloat16(v.w);
    __nv_bfloat16 l0 = __float2bfloat16(v.x - __bfloat162float(h0));
    __nv_bfloat16 l1 = __float2bfloat16(v.y - __bfloat162float(h1));
    __nv_bfloat16 l2 = __float2bfloat16(v.z - __bfloat162float(h2));
    __nv_bfloat16 l3 = __float2bfloat16(v.w - __bfloat162float(h3));
    ((__nv_bfloat162*)hi)[2 * i]     = __nv_bfloat162(h0, h1);
    ((__nv_bfloat162*)hi)[2 * i + 1] = __nv_bfloat162(h2, h3);
    ((__nv_bfloat162*)lo)[2 * i]     = __nv_bfloat162(l0, l1);
    ((__nv_bfloat162*)lo)[2 * i + 1] = __nv_bfloat162(l2, l3);
}

// ---------------------------------------------------------------------------
// Kernel 1: deterministic mask compaction
// ---------------------------------------------------------------------------
__global__ __launch_bounds__(1024) void build_idx_kernel(
    const int* __restrict__ kp, const int* __restrict__ am,
    int* __restrict__ idx, int* __restrict__ counts)
{
    __shared__ int ssum[1024];
    const int b = blockIdx.x;
    const int t = threadIdx.x;
    const int base = b * SS;
    const int s0 = 2 * t, s1 = 2 * t + 1;
    int v0 = (kp[base + s0] == 0 && am[base + s0] == 0) ? 1 : 0;
    int v1 = (kp[base + s1] == 0 && am[base + s1] == 0) ? 1 : 0;
    ssum[t] = v0 + v1;
    __syncthreads();
    for (int off = 1; off < 1024; off <<= 1) {
        int add = (t >= off) ? ssum[t - off] : 0;
        int val = ssum[t];
        __syncthreads();
        ssum[t] = val + add;
        __syncthreads();
    }
    int excl = ssum[t] - (v0 + v1);
    if (v0) idx[base + excl]      = base + s0;
    if (v1) idx[base + excl + v0] = base + s1;
    if (t == 1023) counts[b] = ssum[1023];
}

// ---------------------------------------------------------------------------
// Kernel 2: HMMA GEMM  out[m,n] = (sum_k A[m,k]*W[n,k] + bias[n]) * scale
// hi/lo split: 3 MMA products, fp32 accum. Output either fp32 (Cf) or
// bf16 hi/lo pair (Chi/Clo).
// ---------------------------------------------------------------------------
#define GSTAGE 65536
#define GSM_BYTES (2 * GSTAGE)

__global__ __launch_bounds__(256, 1) void gemm_mma_kernel(
    const __nv_bfloat16* __restrict__ Ahi, const __nv_bfloat16* __restrict__ Alo,
    const __nv_bfloat16* __restrict__ Bhi, const __nv_bfloat16* __restrict__ Blo,
    const float* __restrict__ bias, float scale,
    float* __restrict__ Cf,
    __nv_bfloat16* __restrict__ Chi, __nv_bfloat16* __restrict__ Clo,
    const int* __restrict__ gather, const int* __restrict__ counts)
{
    extern __shared__ char smem[];
    const uint32_t sb = (uint32_t)__cvta_generic_to_shared(smem);
    const int nBase = blockIdx.x * 128;
    const int mBase = blockIdx.y * 128;
    int cnt = 0;
    if (gather) {
        cnt = counts[mBase >> 11];
        if ((mBase & 2047) >= cnt) return;
    }
    const int t    = threadIdx.x;
    const int wid  = t >> 5;
    const int lane = t & 31;
    const int wm   = wid >> 1;
    const int wn   = wid & 1;

    const int sRow  = t >> 1;
    const int uBase = (t & 1) * 4;
    int srcRow;
    {
        int m = mBase + sRow;
        if (gather) {
            bool ok = (m & 2047) < cnt;
            srcRow = ok ? gather[m] : ((m >> 11) * SS);
        } else {
            srcRow = m;
        }
    }
    const __nv_bfloat16* aHp = Ahi + (size_t)srcRow * DD;
    const __nv_bfloat16* aLp = Alo + (size_t)srcRow * DD;
    const __nv_bfloat16* bHp = Bhi + (size_t)(nBase + sRow) * DD;
    const __nv_bfloat16* bLp = Blo + (size_t)(nBase + sRow) * DD;
    uint32_t stOff[4];
#pragma unroll
    for (int i = 0; i < 4; i++)
        stOff[i] = sRow * 128 + (((uBase + i) ^ (sRow & 7)) << 4);

    const int g  = lane >> 3;
    const int lr = lane & 7;
    const uint32_t rowA = wm * 32 + (g & 1) * 8 + lr;
    const uint32_t rxa  = rowA & 7;
    const uint32_t aoff = rowA * 128;
    const int aU = g >> 1;
    const uint32_t rowB = wn * 64 + (g >> 1) * 8 + lr;
    const uint32_t rxb  = rowB & 7;
    const uint32_t boff = rowB * 128;
    const int bU = g & 1;

    float acc[2][8][4];
#pragma unroll
    for (int mt = 0; mt < 2; mt++)
#pragma unroll
        for (int j = 0; j < 8; j++)
#pragma unroll
            for (int r = 0; r < 4; r++) acc[mt][j][r] = 0.f;

    {
        const uint32_t s0 = sb;
#pragma unroll
        for (int i = 0; i < 4; i++) {
            int kk = (uBase + i) * 8;
            cp16(s0 +         stOff[i], aHp + kk);
            cp16(s0 + 16384 + stOff[i], aLp + kk);
            cp16(s0 + 32768 + stOff[i], bHp + kk);
            cp16(s0 + 49152 + stOff[i], bLp + kk);
        }
        cp_commit();
    }

    for (int c = 0; c < 16; c++) {
        cp_wait0();
        __syncthreads();
        if (c + 1 < 16) {
            const uint32_t sN = sb + ((c + 1) & 1) * GSTAGE;
            const int k0 = (c + 1) * 64;
#pragma unroll
            for (int i = 0; i < 4; i++) {
                int kk = k0 + (uBase + i) * 8;
                cp16(sN +         stOff[i], aHp + kk);
                cp16(sN + 16384 + stOff[i], aLp + kk);
                cp16(sN + 32768 + stOff[i], bHp + kk);
                cp16(sN + 49152 + stOff[i], bLp + kk);
            }
            cp_commit();
        }

        const uint32_t base = sb + (c & 1) * GSTAGE;
        const uint32_t tAh = base, tAl = base + 16384;
        const uint32_t tBh = base + 32768, tBl = base + 49152;

#pragma unroll
        for (int ks = 0; ks < 4; ks++) {
            uint32_t ah[2][4], al[2][4];
#pragma unroll
            for (int mt = 0; mt < 2; mt++) {
                uint32_t sw = (((2 * ks + aU) ^ rxa) << 4);
                ldmx4(ah[mt], tAh + aoff + mt * 2048 + sw);
                ldmx4(al[mt], tAl + aoff + mt * 2048 + sw);
            }
            uint32_t bh[8][2], bl[8][2];
#pragma unroll
            for (int jp = 0; jp < 4; jp++) {
                uint32_t sw = (((2 * ks + bU) ^ rxb) << 4);
                uint32_t r4[4];
                ldmx4(r4, tBh + boff + jp * 2048 + sw);
                bh[2 * jp][0] = r4[0]; bh[2 * jp][1] = r4[1];
                bh[2 * jp + 1][0] = r4[2]; bh[2 * jp + 1][1] = r4[3];
                ldmx4(r4, tBl + boff + jp * 2048 + sw);
                bl[2 * jp][0] = r4[0]; bl[2 * jp][1] = r4[1];
                bl[2 * jp + 1][0] = r4[2]; bl[2 * jp + 1][1] = r4[3];
            }
#pragma unroll
            for (int mt = 0; mt < 2; mt++)
#pragma unroll
                for (int j = 0; j < 8; j++) {
                    mma_bf16(acc[mt][j], ah[mt], bh[j]);
                    mma_bf16(acc[mt][j], ah[mt], bl[j]);
                    mma_bf16(acc[mt][j], al[mt], bh[j]);
                }
        }
        __syncthreads();
    }

#pragma unroll
    for (int mt = 0; mt < 2; mt++) {
        int m0 = mBase + wm * 32 + mt * 16 + (lane >> 2);
        int m1 = m0 + 8;
        bool ok0 = true, ok1 = true;
        if (gather) {
            ok0 = (m0 & 2047) < cnt;
            ok1 = (m1 & 2047) < cnt;
        }
#pragma unroll
        for (int j = 0; j < 8; j++) {
            int n = nBase + wn * 64 + j * 8 + 2 * (lane & 3);
            float b0v = bias[n], b1v = bias[n + 1];
            float o00 = (acc[mt][j][0] + b0v) * scale;
            float o01 = (acc[mt][j][1] + b1v) * scale;
            float o10 = (acc[mt][j][2] + b0v) * scale;
            float o11 = (acc[mt][j][3] + b1v) * scale;
            if (Cf) {
                if (ok0) *(float2*)&Cf[(size_t)m0 * DD + n] = make_float2(o00, o01);
                if (ok1) *(float2*)&Cf[(size_t)m1 * DD + n] = make_float2(o10, o11);
            } else {
                if (ok0) {
                    __nv_bfloat16 h0 = __float2bfloat16(o00), h1 = __float2bfloat16(o01);
                    *(__nv_bfloat162*)&Chi[(size_t)m0 * DD + n] = __nv_bfloat162(h0, h1);
                    *(__nv_bfloat162*)&Clo[(size_t)m0 * DD + n] = __nv_bfloat162(
                        __float2bfloat16(o00 - __bfloat162float(h0)),
                        __float2bfloat16(o01 - __bfloat162float(h1)));
                }
                if (ok1) {
                    __nv_bfloat16 h0 = __float2bfloat16(o10), h1 = __float2bfloat16(o11);
                    *(__nv_bfloat162*)&Chi[(size_t)m1 * DD + n] = __nv_bfloat162(h0, h1);
                    *(__nv_bfloat162*)&Clo[(size_t)m1 * DD + n] = __nv_bfloat162(
                        __float2bfloat16(o10 - __bfloat162float(h0)),
                        __float2bfloat16(o11 - __bfloat162float(h1)));
                }
            }
        }
    }
}

// ---------------------------------------------------------------------------
// Kernel 3: tensor-core flash attention (mma.sync bf16, hi/lo split)
// CTA: 64 q-rows x (head, batch); 4 warps x 16 rows; 64-key blocks; hd=64.
// Smem: Qh|Ql (8K each) | Kh[2]|Kl[2]|Vh[2]|Vl[2] (8K per buffer) = 80KB.
// All tiles: 64 rows x 128 bytes, XOR-swizzled on 16B units (u ^= row&7).
// ---------------------------------------------------------------------------
#define ASM_QH 0
#define ASM_QL 8192
#define ASM_KH 16384
#define ASM_KL 32768
#define ASM_VH 49152
#define ASM_VL 65536
#define ATTN_SMEM 81920

__global__ __launch_bounds__(128) void attn_mma_kernel(
    const __nv_bfloat16* __restrict__ Qh_, const __nv_bfloat16* __restrict__ Ql_,
    const __nv_bfloat16* __restrict__ Kh_, const __nv_bfloat16* __restrict__ Kl_,
    const __nv_bfloat16* __restrict__ Vh_, const __nv_bfloat16* __restrict__ Vl_,
    __nv_bfloat16* __restrict__ Oh_, __nv_bfloat16* __restrict__ Ol_,
    const int* __restrict__ counts)
{
    extern __shared__ char smem[];
    const uint32_t sb = (uint32_t)__cvta_generic_to_shared(smem);
    const int qb = blockIdx.x, h = blockIdx.y, b = blockIdx.z;
    const int t = threadIdx.x, w = t >> 5, lane = t & 31;
    const int q0 = qb * 64;
    const int cnt = counts[b];
    const int nb = (cnt + 63) >> 6;

    const int sRow = t >> 1, uB = (t & 1) * 4;
    const size_t hoff = (size_t)h * HDIM;

    auto stage_tile = [&](uint32_t dstBase, const __nv_bfloat16* src) {
        const __nv_bfloat16* gp = src + (size_t)sRow * DD;
#pragma unroll
        for (int i = 0; i < 4; i++) {
            int u = uB + i;
            cp16(dstBase + sRow * 128 + ((u ^ (sRow & 7)) << 4), gp + u * 8);
        }
    };

    // prologue: Q tiles + k-block 0
    stage_tile(sb + ASM_QH, Qh_ + (size_t)(b * SS + q0) * DD + hoff);
    stage_tile(sb + ASM_QL, Ql_ + (size_t)(b * SS + q0) * DD + hoff);
    stage_tile(sb + ASM_KH, Kh_ + (size_t)(b * SS) * DD + hoff);
    stage_tile(sb + ASM_KL, Kl_ + (size_t)(b * SS) * DD + hoff);
    stage_tile(sb + ASM_VH, Vh_ + (size_t)(b * SS) * DD + hoff);
    stage_tile(sb + ASM_VL, Vl_ + (size_t)(b * SS) * DD + hoff);
    cp_commit();

    // fragment lane geometry
    const int g  = lane >> 3;
    const int lr = lane & 7;
    const uint32_t rowA = w * 16 + (g & 1) * 8 + lr;   // Q rows (A operand)
    const uint32_t rxa  = rowA & 7;
    const uint32_t aoff = rowA * 128;
    const int aU = g >> 1;
    const uint32_t rowB = (g >> 1) * 8 + lr;           // K rows (B non-trans)
    const uint32_t rxb  = rowB & 7;
    const int bU = g & 1;
    const uint32_t rowV = (g & 1) * 8 + lr;            // V rows (B trans, rows=keys)
    const uint32_t rxv  = rowV & 7;
    const int vU = g >> 1;

    float m0 = -1e30f, m1 = -1e30f, l0 = 0.f, l1 = 0.f;
    float oacc[8][4];
#pragma unroll
    for (int j = 0; j < 8; j++)
#pragma unroll
        for (int r = 0; r < 4; r++) oacc[j][r] = 0.f;

    int buf = 0;
    for (int kb = 0; kb < nb; kb++) {
        cp_wait0();
        __syncthreads();
        if (kb + 1 < nb) {
            const size_t rbase = (size_t)(b * SS + (kb + 1) * 64) * DD + hoff;
            const uint32_t o = (buf ^ 1) * 8192;
            stage_tile(sb + ASM_KH + o, Kh_ + rbase);
            stage_tile(sb + ASM_KL + o, Kl_ + rbase);
            stage_tile(sb + ASM_VH + o, Vh_ + rbase);
            stage_tile(sb + ASM_VL + o, Vl_ + rbase);
            cp_commit();
        }

        const uint32_t tKH = sb + ASM_KH + buf * 8192;
        const uint32_t tKL = sb + ASM_KL + buf * 8192;

        // ---- S = Q K^T (hi/lo, fp32 accum); Q already scaled by 1/8
        float sacc[8][4];
#pragma unroll
        for (int j = 0; j < 8; j++)
#pragma unroll
            for (int r = 0; r < 4; r++) sacc[j][r] = 0.f;
#pragma unroll
        for (int ks = 0; ks < 4; ks++) {
            uint32_t ah[4], al[4];
            const uint32_t swA = ((2 * ks + aU) ^ rxa) << 4;
            ldmx4(ah, sb + ASM_QH + aoff + swA);
            ldmx4(al, sb + ASM_QL + aoff + swA);
            uint32_t bh[8][2], bl[8][2];
#pragma unroll
            for (int jp = 0; jp < 4; jp++) {
                const uint32_t addr = (rowB + 16 * jp) * 128 + (((2 * ks + bU) ^ rxb) << 4);
                uint32_t r4[4];
                ldmx4(r4, tKH + addr);
                bh[2 * jp][0] = r4[0]; bh[2 * jp][1] = r4[1];
                bh[2 * jp + 1][0] = r4[2]; bh[2 * jp + 1][1] = r4[3];
                ldmx4(r4, tKL + addr);
                bl[2 * jp][0] = r4[0]; bl[2 * jp][1] = r4[1];
                bl[2 * jp + 1][0] = r4[2]; bl[2 * jp + 1][1] = r4[3];
            }
#pragma unroll
            for (int j = 0; j < 8; j++) {
                mma_bf16(sacc[j], ah, bh[j]);
                mma_bf16(sacc[j], ah, bl[j]);
                mma_bf16(sacc[j], al, bh[j]);
            }
        }

        // ---- mask tail keys
        const int kcol = kb * 64 + 2 * (lane & 3);
#pragma unroll
        for (int j = 0; j < 8; j++) {
            const int kc = kcol + 8 * j;
            if (kc >= cnt)     { sacc[j][0] = -1e30f; sacc[j][2] = -1e30f; }
            if (kc + 1 >= cnt) { sacc[j][1] = -1e30f; sacc[j][3] = -1e30f; }
        }

        // ---- online softmax (rows: lane>>2 and +8; quad shfl reduce)
        float rm0 = -1e30f, rm1 = -1e30f;
#pragma unroll
        for (int j = 0; j < 8; j++) {
            rm0 = fmaxf(rm0, fmaxf(sacc[j][0], sacc[j][1]));
            rm1 = fmaxf(rm1, fmaxf(sacc[j][2], sacc[j][3]));
        }
        rm0 = fmaxf(rm0, __shfl_xor_sync(0xffffffffu, rm0, 1));
        rm0 = fmaxf(rm0, __shfl_xor_sync(0xffffffffu, rm0, 2));
        rm1 = fmaxf(rm1, __shfl_xor_sync(0xffffffffu, rm1, 1));
        rm1 = fmaxf(rm1, __shfl_xor_sync(0xffffffffu, rm1, 2));
        const float nm0 = fmaxf(m0, rm0), nm1 = fmaxf(m1, rm1);
        const float c0 = __expf(m0 - nm0), c1 = __expf(m1 - nm1);
        m0 = nm0; m1 = nm1;
        float rs0 = 0.f, rs1 = 0.f;
#pragma unroll
        for (int j = 0; j < 8; j++) {
            sacc[j][0] = __expf(sacc[j][0] - nm0);
            sacc[j][1] = __expf(sacc[j][1] - nm0);
            sacc[j][2] = __expf(sacc[j][2] - nm1);
            sacc[j][3] = __expf(sacc[j][3] - nm1);
            rs0 += sacc[j][0] + sacc[j][1];
            rs1 += sacc[j][2] + sacc[j][3];
        }
        rs0 += __shfl_xor_sync(0xffffffffu, rs0, 1);
        rs0 += __shfl_xor_sync(0xffffffffu, rs0, 2);
        rs1 += __shfl_xor_sync(0xffffffffu, rs1, 1);
        rs1 += __shfl_xor_sync(0xffffffffu, rs1, 2);
        l0 = l0 * c0 + rs0;
        l1 = l1 * c1 + rs1;
#pragma unroll
        for (int j = 0; j < 8; j++) {
            oacc[j][0] *= c0; oacc[j][1] *= c0;
            oacc[j][2] *= c1; oacc[j][3] *= c1;
        }

        // ---- O += P V (hi/lo; P fragments straight from sacc, V via trans)
        const uint32_t tVH = sb + ASM_VH + buf * 8192;
        const uint32_t tVL = sb + ASM_VL + buf * 8192;
#pragma unroll
        for (int ks = 0; ks < 4; ks++) {
            const int nt0 = 2 * ks, nt1 = 2 * ks + 1;
            uint32_t aPh[4], aPl[4];
            {
                float p00 = sacc[nt0][0], p01 = sacc[nt0][1];
                float p02 = sacc[nt0][2], p03 = sacc[nt0][3];
                float p10 = sacc[nt1][0], p11 = sacc[nt1][1];
                float p12 = sacc[nt1][2], p13 = sacc[nt1][3];
                __nv_bfloat16 h00 = __float2bfloat16(p00), h01 = __float2bfloat16(p01);
                __nv_bfloat16 h02 = __float2bfloat16(p02), h03 = __float2bfloat16(p03);
                __nv_bfloat16 h10 = __float2bfloat16(p10), h11 = __float2bfloat16(p11);
                __nv_bfloat16 h12 = __float2bfloat16(p12), h13 = __float2bfloat16(p13);
                __nv_bfloat162 v0(h00, h01), v1(h02, h03), v2(h10, h11), v3(h12, h13);
                aPh[0] = *(uint32_t*)&v0; aPh[1] = *(uint32_t*)&v1;
                aPh[2] = *(uint32_t*)&v2; aPh[3] = *(uint32_t*)&v3;
                aPl[0] = pack_bf16(p00 - __bfloat162float(h00), p01 - __bfloat162float(h01));
                aPl[1] = pack_bf16(p02 - __bfloat162float(h02), p03 - __bfloat162float(h03));
                aPl[2] = pack_bf16(p10 - __bfloat162float(h10), p11 - __bfloat162float(h11));
                aPl[3] = pack_bf16(p12 - __bfloat162float(h12), p13 - __bfloat162float(h13));
            }
            uint32_t bvh[8][2], bvl[8][2];
#pragma unroll
            for (int dp = 0; dp < 4; dp++) {
                const uint32_t addr = (rowV + 16 * ks) * 128 + (((2 * dp + vU) ^ rxv) << 4);
                uint32_t r4[4];
                ldmx4t(r4, tVH + addr);
                bvh[2 * dp][0] = r4[0]; bvh[2 * dp][1] = r4[1];
                bvh[2 * dp + 1][0] = r4[2]; bvh[2 * dp + 1][1] = r4[3];
                ldmx4t(r4, tVL + addr);
                bvl[2 * dp][0] = r4[0]; bvl[2 * dp][1] = r4[1];
                bvl[2 * dp + 1][0] = r4[2]; bvl[2 * dp + 1][1] = r4[3];
            }
#pragma unroll
            for (int j = 0; j < 8; j++) {
                mma_bf16(oacc[j], aPh, bvh[j]);
                mma_bf16(oacc[j], aPh, bvl[j]);
                mma_bf16(oacc[j], aPl, bvh[j]);
            }
        }
        buf ^= 1;
    }

    // ---- epilogue: normalize, split to bf16 hi/lo, store
    const float inv0 = 1.0f / l0, inv1 = 1.0f / l1;
    const int row0 = b * SS + q0 + w * 16 + (lane >> 2);
    const int row1 = row0 + 8;
    const int dbase = h * HDIM + 2 * (lane & 3);
#pragma unroll
    for (int j = 0; j < 8; j++) {
        float o00 = oacc[j][0] * inv0, o01 = oacc[j][1] * inv0;
        float o10 = oacc[j][2] * inv1, o11 = oacc[j][3] * inv1;
        __nv_bfloat16 h00 = __float2bfloat16(o00), h01 = __float2bfloat16(o01);
        __nv_bfloat16 h10 = __float2bfloat16(o10), h11 = __float2bfloat16(o11);
        size_t a0 = (size_t)row0 * DD + dbase + 8 * j;
        size_t a1 = (size_t)row1 * DD + dbase + 8 * j;
        *(__nv_bfloat162*)&Oh_[a0] = __nv_bfloat162(h00, h01);
        *(__nv_bfloat162*)&Ol_[a0] = __nv_bfloat162(
            __float2bfloat16(o00 - __bfloat162float(h00)),
            __float2bfloat16(o01 - __bfloat162float(h01)));
        *(__nv_bfloat162*)&Oh_[a1] = __nv_bfloat162(h10, h11);
        *(__nv_bfloat162*)&Ol_[a1] = __nv_bfloat162(
            __float2bfloat16(o10 - __bfloat162float(h10)),
            __float2bfloat16(o11 - __bfloat162float(h11)));
    }
}

// ---------------------------------------------------------------------------
// Launch
// ---------------------------------------------------------------------------
extern "C" void kernel_launch(void* const* d_in, const int* in_sizes, int n_in,
                              void* d_out, int out_size)
{
    (void)out_size;
    const float* qkv[3]   = {nullptr, nullptr, nullptr};
    const int*   masks[2] = {nullptr, nullptr};
    const float* Ws[4]    = {nullptr, nullptr, nullptr, nullptr};
    const float* bs[4]    = {nullptr, nullptr, nullptr, nullptr};
    int nqkv = 0, nmask = 0, nW = 0, nb = 0;
    for (int i = 0; i < n_in; i++) {
        int sz = in_sizes[i];
        if (sz == MTOT * DD && nqkv < 3)      qkv[nqkv++] = (const float*)d_in[i];
        else if (sz == MTOT && nmask < 2)     masks[nmask++] = (const int*)d_in[i];
        else if (sz == DD * DD && nW < 4)     Ws[nW++] = (const float*)d_in[i];
        else if (sz == DD && nb < 4)          bs[nb++] = (const float*)d_in[i];
    }

    static int attr_done = 0;
    if (!attr_done) {
        cudaFuncSetAttribute(gemm_mma_kernel,
                             cudaFuncAttributeMaxDynamicSharedMemorySize, GSM_BYTES);
        cudaFuncSetAttribute(attn_mma_kernel,
                             cudaFuncAttributeMaxDynamicSharedMemorySize, ATTN_SMEM);
        attr_done = 1;
    }

    int *gidx, *gcnt;
    __nv_bfloat16 *qh, *ql, *kh, *kl, *vh, *vl, *wh, *wl;
    __nv_bfloat16 *pqh, *pql, *pkh, *pkl, *pvh, *pvl, *ah, *al;
    cudaGetSymbolAddress((void**)&gidx, g_idx);
    cudaGetSymbolAddress((void**)&gcnt, g_cnt);
    cudaGetSymbolAddress((void**)&qh, g_qh); cudaGetSymbolAddress((void**)&ql, g_ql);
    cudaGetSymbolAddress((void**)&kh, g_kh); cudaGetSymbolAddress((void**)&kl, g_kl);
    cudaGetSymbolAddress((void**)&vh, g_vh); cudaGetSymbolAddress((void**)&vl, g_vl);
    cudaGetSymbolAddress((void**)&wh, g_Wh); cudaGetSymbolAddress((void**)&wl, g_Wl);
    cudaGetSymbolAddress((void**)&pqh, g_pqh); cudaGetSymbolAddress((void**)&pql, g_pql);
    cudaGetSymbolAddress((void**)&pkh, g_pkh); cudaGetSymbolAddress((void**)&pkl, g_pkl);
    cudaGetSymbolAddress((void**)&pvh, g_pvh); cudaGetSymbolAddress((void**)&pvl, g_pvl);
    cudaGetSymbolAddress((void**)&ah, g_ah);   cudaGetSymbolAddress((void**)&al, g_al);

    const int N4_ACT = MTOT * DD / 4;
    const int N4_W   = DD * DD / 4;
    dim3 mmaGrid(DD / 128, MTOT / 128); // (8, 32)

    build_idx_kernel<<<BB, 1024>>>(masks[0], masks[1], gidx, gcnt);

    conv_split_kernel<<<(N4_ACT + 255) / 256, 256>>>(qkv[0], qh, ql, N4_ACT);
    conv_split_kernel<<<(N4_ACT + 255) / 256, 256>>>(qkv[1], kh, kl, N4_ACT);
    conv_split_kernel<<<(N4_ACT + 255) / 256, 256>>>(qkv[2], vh, vl, N4_ACT);
    for (int w = 0; w < 4; w++)
        conv_split_kernel<<<(N4_W + 255) / 256, 256>>>(
            Ws[w], wh + (size_t)w * DD * DD, wl + (size_t)w * DD * DD, N4_W);

    // projections -> bf16 hi/lo (Q pre-scaled by 1/sqrt(64))
    gemm_mma_kernel<<<mmaGrid, 256, GSM_BYTES>>>(qh, ql, wh, wl, bs[0], 0.125f,
                                                 nullptr, pqh, pql, nullptr, nullptr);
    gemm_mma_kernel<<<mmaGrid, 256, GSM_BYTES>>>(kh, kl, wh + (size_t)1 * DD * DD,
                                                 wl + (size_t)1 * DD * DD, bs[1], 1.0f,
                                                 nullptr, pkh, pkl, gidx, gcnt);
    gemm_mma_kernel<<<mmaGrid, 256, GSM_BYTES>>>(vh, vl, wh + (size_t)2 * DD * DD,
                                                 wl + (size_t)2 * DD * DD, bs[2], 1.0f,
                                                 nullptr, pvh, pvl, gidx, gcnt);

    attn_mma_kernel<<<dim3(SS / 64, HH, BB), 128, ATTN_SMEM>>>(
        pqh, pql, pkh, pkl, pvh, pvl, ah, al, gcnt);

    // output projection -> fp32 d_out
    gemm_mma_kernel<<<mmaGrid, 256, GSM_BYTES>>>(ah, al, wh + (size_t)3 * DD * DD,
                                                 wl + (size_t)3 * DD * DD, bs[3], 1.0f,
                                                 (float*)d_out, nullptr, nullptr,
                                                 nullptr, nullptr);
}

// round 7
// speedup vs baseline: 2.7119x; 1.0014x over previous
#include <cuda_runtime.h>
#include <cuda_bf16.h>
#include <cstdint>
#include <cstddef>

// Problem constants
#define BB 2
#define SS 2048
#define DD 1024
#define HH 16
#define HDIM 64
#define MTOT (BB * SS) // 4096

// ---------------------------------------------------------------------------
// Scratch (device globals)
// ---------------------------------------------------------------------------
__device__ int g_idx[MTOT];
__device__ int g_cnt[BB];
__device__ __nv_bfloat16 g_qh[(size_t)MTOT * DD], g_ql[(size_t)MTOT * DD];
__device__ __nv_bfloat16 g_kh[(size_t)MTOT * DD], g_kl[(size_t)MTOT * DD];
__device__ __nv_bfloat16 g_vh[(size_t)MTOT * DD], g_vl[(size_t)MTOT * DD];
__device__ __nv_bfloat16 g_Wh[4][(size_t)DD * DD], g_Wl[4][(size_t)DD * DD];
__device__ __nv_bfloat16 g_pqh[(size_t)MTOT * DD], g_pql[(size_t)MTOT * DD];
__device__ __nv_bfloat16 g_pkh[(size_t)MTOT * DD], g_pkl[(size_t)MTOT * DD];
__device__ __nv_bfloat16 g_pvh[(size_t)MTOT * DD], g_pvl[(size_t)MTOT * DD];
__device__ __nv_bfloat16 g_ah[(size_t)MTOT * DD], g_al[(size_t)MTOT * DD];

// ---------------------------------------------------------------------------
// PTX helpers
// ---------------------------------------------------------------------------
__device__ __forceinline__ void cp16(unsigned dst, const void* src) {
    asm volatile("cp.async.cg.shared.global [%0], [%1], 16;" :: "r"(dst), "l"(src));
}
__device__ __forceinline__ void cp_commit() { asm volatile("cp.async.commit_group;"); }
__device__ __forceinline__ void cp_wait0()  { asm volatile("cp.async.wait_group 0;" ::: "memory"); }

__device__ __forceinline__ void ldmx4(uint32_t* r, uint32_t addr) {
    asm volatile("ldmatrix.sync.aligned.m8n8.x4.shared.b16 {%0,%1,%2,%3}, [%4];"
                 : "=r"(r[0]), "=r"(r[1]), "=r"(r[2]), "=r"(r[3]) : "r"(addr));
}
__device__ __forceinline__ void ldmx4t(uint32_t* r, uint32_t addr) {
    asm volatile("ldmatrix.sync.aligned.m8n8.x4.trans.shared.b16 {%0,%1,%2,%3}, [%4];"
                 : "=r"(r[0]), "=r"(r[1]), "=r"(r[2]), "=r"(r[3]) : "r"(addr));
}
__device__ __forceinline__ void mma_bf16(float* d, const uint32_t* a, const uint32_t* b) {
    asm volatile(
        "mma.sync.aligned.m16n8k16.row.col.f32.bf16.bf16.f32 "
        "{%0,%1,%2,%3}, {%4,%5,%6,%7}, {%8,%9}, {%0,%1,%2,%3};"
        : "+f"(d[0]), "+f"(d[1]), "+f"(d[2]), "+f"(d[3])
        : "r"(a[0]), "r"(a[1]), "r"(a[2]), "r"(a[3]), "r"(b[0]), "r"(b[1]));
}
__device__ __forceinline__ uint32_t pack_bf16(float a, float b) {
    __nv_bfloat162 v(__float2bfloat16(a), __float2bfloat16(b));
    return *(uint32_t*)&v;
}
__device__ __forceinline__ float ex2(float x) {
    float r;
    asm("ex2.approx.f32 %0, %1;" : "=f"(r) : "f"(x));
    return r;
}

// ---------------------------------------------------------------------------
// Kernel: fp32 -> bf16 (hi, lo) split, 8 elements/thread (16B stores)
// ---------------------------------------------------------------------------
__global__ __launch_bounds__(256) void conv_split_kernel(
    const float* __restrict__ x, __nv_bfloat16* __restrict__ hi,
    __nv_bfloat16* __restrict__ lo, int n8)
{
    int i = blockIdx.x * blockDim.x + threadIdx.x;
    if (i >= n8) return;
    float4 v0 = ((const float4*)x)[2 * i];
    float4 v1 = ((const float4*)x)[2 * i + 1];
    float f[8] = {v0.x, v0.y, v0.z, v0.w, v1.x, v1.y, v1.z, v1.w};
    uint32_t hp[4], lp[4];
#pragma unroll
    for (int j = 0; j < 4; j++) {
        __nv_bfloat16 h0 = __float2bfloat16(f[2 * j]);
        __nv_bfloat16 h1 = __float2bfloat16(f[2 * j + 1]);
        __nv_bfloat162 hv(h0, h1);
        hp[j] = *(uint32_t*)&hv;
        lp[j] = pack_bf16(f[2 * j] - __bfloat162float(h0),
                          f[2 * j + 1] - __bfloat162float(h1));
    }
    ((uint4*)hi)[i] = make_uint4(hp[0], hp[1], hp[2], hp[3]);
    ((uint4*)lo)[i] = make_uint4(lp[0], lp[1], lp[2], lp[3]);
}

// ---------------------------------------------------------------------------
// Kernel 1: deterministic mask compaction
// ---------------------------------------------------------------------------
__global__ __launch_bounds__(1024) void build_idx_kernel(
    const int* __restrict__ kp, const int* __restrict__ am,
    int* __restrict__ idx, int* __restrict__ counts)
{
    __shared__ int ssum[1024];
    const int b = blockIdx.x;
    const int t = threadIdx.x;
    const int base = b * SS;
    const int s0 = 2 * t, s1 = 2 * t + 1;
    int v0 = (kp[base + s0] == 0 && am[base + s0] == 0) ? 1 : 0;
    int v1 = (kp[base + s1] == 0 && am[base + s1] == 0) ? 1 : 0;
    ssum[t] = v0 + v1;
    __syncthreads();
    for (int off = 1; off < 1024; off <<= 1) {
        int add = (t >= off) ? ssum[t - off] : 0;
        int val = ssum[t];
        __syncthreads();
        ssum[t] = val + add;
        __syncthreads();
    }
    int excl = ssum[t] - (v0 + v1);
    if (v0) idx[base + excl]      = base + s0;
    if (v1) idx[base + excl + v0] = base + s1;
    if (t == 1023) counts[b] = ssum[1023];
}

// ---------------------------------------------------------------------------
// Kernel 2: HMMA GEMM  out[m,n] = (sum_k A[m,k]*W[n,k] + bias[n]) * scale
// ---------------------------------------------------------------------------
#define GSTAGE 65536
#define GSM_BYTES (2 * GSTAGE)

__global__ __launch_bounds__(256, 1) void gemm_mma_kernel(
    const __nv_bfloat16* __restrict__ Ahi, const __nv_bfloat16* __restrict__ Alo,
    const __nv_bfloat16* __restrict__ Bhi, const __nv_bfloat16* __restrict__ Blo,
    const float* __restrict__ bias, float scale,
    float* __restrict__ Cf,
    __nv_bfloat16* __restrict__ Chi, __nv_bfloat16* __restrict__ Clo,
    const int* __restrict__ gather, const int* __restrict__ counts)
{
    extern __shared__ char smem[];
    const uint32_t sb = (uint32_t)__cvta_generic_to_shared(smem);
    const int nBase = blockIdx.x * 128;
    const int mBase = blockIdx.y * 128;
    int cnt = 0;
    if (gather) {
        cnt = counts[mBase >> 11];
        if ((mBase & 2047) >= cnt) return;
    }
    const int t    = threadIdx.x;
    const int wid  = t >> 5;
    const int lane = t & 31;
    const int wm   = wid >> 1;
    const int wn   = wid & 1;

    const int sRow  = t >> 1;
    const int uBase = (t & 1) * 4;
    int srcRow;
    {
        int m = mBase + sRow;
        if (gather) {
            bool ok = (m & 2047) < cnt;
            srcRow = ok ? gather[m] : ((m >> 11) * SS);
        } else {
            srcRow = m;
        }
    }
    const __nv_bfloat16* aHp = Ahi + (size_t)srcRow * DD;
    const __nv_bfloat16* aLp = Alo + (size_t)srcRow * DD;
    const __nv_bfloat16* bHp = Bhi + (size_t)(nBase + sRow) * DD;
    const __nv_bfloat16* bLp = Blo + (size_t)(nBase + sRow) * DD;
    uint32_t stOff[4];
#pragma unroll
    for (int i = 0; i < 4; i++)
        stOff[i] = sRow * 128 + (((uBase + i) ^ (sRow & 7)) << 4);

    const int g  = lane >> 3;
    const int lr = lane & 7;
    const uint32_t rowA = wm * 32 + (g & 1) * 8 + lr;
    const uint32_t rxa  = rowA & 7;
    const uint32_t aoff = rowA * 128;
    const int aU = g >> 1;
    const uint32_t rowB = wn * 64 + (g >> 1) * 8 + lr;
    const uint32_t rxb  = rowB & 7;
    const uint32_t boff = rowB * 128;
    const int bU = g & 1;

    float acc[2][8][4];
#pragma unroll
    for (int mt = 0; mt < 2; mt++)
#pragma unroll
        for (int j = 0; j < 8; j++)
#pragma unroll
            for (int r = 0; r < 4; r++) acc[mt][j][r] = 0.f;

    {
        const uint32_t s0 = sb;
#pragma unroll
        for (int i = 0; i < 4; i++) {
            int kk = (uBase + i) * 8;
            cp16(s0 +         stOff[i], aHp + kk);
            cp16(s0 + 16384 + stOff[i], aLp + kk);
            cp16(s0 + 32768 + stOff[i], bHp + kk);
            cp16(s0 + 49152 + stOff[i], bLp + kk);
        }
        cp_commit();
    }

    for (int c = 0; c < 16; c++) {
        cp_wait0();
        __syncthreads();
        if (c + 1 < 16) {
            const uint32_t sN = sb + ((c + 1) & 1) * GSTAGE;
            const int k0 = (c + 1) * 64;
#pragma unroll
            for (int i = 0; i < 4; i++) {
                int kk = k0 + (uBase + i) * 8;
                cp16(sN +         stOff[i], aHp + kk);
                cp16(sN + 16384 + stOff[i], aLp + kk);
                cp16(sN + 32768 + stOff[i], bHp + kk);
                cp16(sN + 49152 + stOff[i], bLp + kk);
            }
            cp_commit();
        }

        const uint32_t base = sb + (c & 1) * GSTAGE;
        const uint32_t tAh = base, tAl = base + 16384;
        const uint32_t tBh = base + 32768, tBl = base + 49152;

#pragma unroll
        for (int ks = 0; ks < 4; ks++) {
            uint32_t ah[2][4], al[2][4];
#pragma unroll
            for (int mt = 0; mt < 2; mt++) {
                uint32_t sw = (((2 * ks + aU) ^ rxa) << 4);
                ldmx4(ah[mt], tAh + aoff + mt * 2048 + sw);
                ldmx4(al[mt], tAl + aoff + mt * 2048 + sw);
            }
            uint32_t bh[8][2], bl[8][2];
#pragma unroll
            for (int jp = 0; jp < 4; jp++) {
                uint32_t sw = (((2 * ks + bU) ^ rxb) << 4);
                uint32_t r4[4];
                ldmx4(r4, tBh + boff + jp * 2048 + sw);
                bh[2 * jp][0] = r4[0]; bh[2 * jp][1] = r4[1];
                bh[2 * jp + 1][0] = r4[2]; bh[2 * jp + 1][1] = r4[3];
                ldmx4(r4, tBl + boff + jp * 2048 + sw);
                bl[2 * jp][0] = r4[0]; bl[2 * jp][1] = r4[1];
                bl[2 * jp + 1][0] = r4[2]; bl[2 * jp + 1][1] = r4[3];
            }
#pragma unroll
            for (int mt = 0; mt < 2; mt++)
#pragma unroll
                for (int j = 0; j < 8; j++) {
                    mma_bf16(acc[mt][j], ah[mt], bh[j]);
                    mma_bf16(acc[mt][j], ah[mt], bl[j]);
                    mma_bf16(acc[mt][j], al[mt], bh[j]);
                }
        }
        __syncthreads();
    }

#pragma unroll
    for (int mt = 0; mt < 2; mt++) {
        int m0 = mBase + wm * 32 + mt * 16 + (lane >> 2);
        int m1 = m0 + 8;
        bool ok0 = true, ok1 = true;
        if (gather) {
            ok0 = (m0 & 2047) < cnt;
            ok1 = (m1 & 2047) < cnt;
        }
#pragma unroll
        for (int j = 0; j < 8; j++) {
            int n = nBase + wn * 64 + j * 8 + 2 * (lane & 3);
            float b0v = bias[n], b1v = bias[n + 1];
            float o00 = (acc[mt][j][0] + b0v) * scale;
            float o01 = (acc[mt][j][1] + b1v) * scale;
            float o10 = (acc[mt][j][2] + b0v) * scale;
            float o11 = (acc[mt][j][3] + b1v) * scale;
            if (Cf) {
                if (ok0) *(float2*)&Cf[(size_t)m0 * DD + n] = make_float2(o00, o01);
                if (ok1) *(float2*)&Cf[(size_t)m1 * DD + n] = make_float2(o10, o11);
            } else {
                if (ok0) {
                    __nv_bfloat16 h0 = __float2bfloat16(o00), h1 = __float2bfloat16(o01);
                    *(__nv_bfloat162*)&Chi[(size_t)m0 * DD + n] = __nv_bfloat162(h0, h1);
                    *(__nv_bfloat162*)&Clo[(size_t)m0 * DD + n] = __nv_bfloat162(
                        __float2bfloat16(o00 - __bfloat162float(h0)),
                        __float2bfloat16(o01 - __bfloat162float(h1)));
                }
                if (ok1) {
                    __nv_bfloat16 h0 = __float2bfloat16(o10), h1 = __float2bfloat16(o11);
                    *(__nv_bfloat162*)&Chi[(size_t)m1 * DD + n] = __nv_bfloat162(h0, h1);
                    *(__nv_bfloat162*)&Clo[(size_t)m1 * DD + n] = __nv_bfloat162(
                        __float2bfloat16(o10 - __bfloat162float(h0)),
                        __float2bfloat16(o11 - __bfloat162float(h1)));
                }
            }
        }
    }
}

// ---------------------------------------------------------------------------
// Kernel 3: tensor-core flash attention (mma.sync bf16, hi/lo)
// CTA: 128 q-rows x (head, batch); 8 warps x 16 rows; 64-key k-blocks.
// Q fragments preloaded into registers (smem recycled as K/V buffers).
// Smem 64KB: KH[2]|KL[2]|VH[2]|VL[2], 8KB per buffer.
// Softmax in exp2 domain (Q pre-scaled by 0.125*log2e in its GEMM).
// ---------------------------------------------------------------------------
#define ASM_KH 0
#define ASM_KL 16384
#define ASM_VH 32768
#define ASM_VL 49152
#define ATTN_SMEM 65536

__global__ __launch_bounds__(256) void attn_mma_kernel(
    const __nv_bfloat16* __restrict__ Qh_, const __nv_bfloat16* __restrict__ Ql_,
    const __nv_bfloat16* __restrict__ Kh_, const __nv_bfloat16* __restrict__ Kl_,
    const __nv_bfloat16* __restrict__ Vh_, const __nv_bfloat16* __restrict__ Vl_,
    __nv_bfloat16* __restrict__ Oh_, __nv_bfloat16* __restrict__ Ol_,
    const int* __restrict__ counts)
{
    extern __shared__ char smem[];
    const uint32_t sb = (uint32_t)__cvta_generic_to_shared(smem);
    const int qb = blockIdx.x, h = blockIdx.y, b = blockIdx.z;
    const int t = threadIdx.x, w = t >> 5, lane = t & 31;
    const int q0 = qb * 128;
    const int cnt = counts[b];
    const int nb = (cnt + 63) >> 6;
    const size_t hoff = (size_t)h * HDIM;

    // fragment lane geometry
    const int g  = lane >> 3;
    const int lr = lane & 7;
    const uint32_t rowA = w * 16 + (g & 1) * 8 + lr;   // Q rows within 128-tile
    const uint32_t rxa  = rowA & 7;
    const uint32_t aoff = rowA * 128;
    const int aU = g >> 1;
    const uint32_t rowB = (g >> 1) * 8 + lr;           // K rows (B non-trans)
    const uint32_t rxb  = rowB & 7;
    const int bU = g & 1;
    const uint32_t rowV = (g & 1) * 8 + lr;            // V rows (B trans)
    const uint32_t rxv  = rowV & 7;
    const int vU = g >> 1;

    // ---- prologue: stage 128-row Q hi/lo into smem (bytes 0..32767)
    {
        const int sRowQ = t >> 1, uBQ = (t & 1) * 4;
        const __nv_bfloat16* qhp = Qh_ + (size_t)(b * SS + q0 + sRowQ) * DD + hoff;
        const __nv_bfloat16* qlp = Ql_ + (size_t)(b * SS + q0 + sRowQ) * DD + hoff;
#pragma unroll
        for (int i = 0; i < 4; i++) {
            int u = uBQ + i;
            uint32_t off = sRowQ * 128 + ((u ^ (sRowQ & 7)) << 4);
            cp16(sb + off,         qhp + u * 8);
            cp16(sb + 16384 + off, qlp + u * 8);
        }
        cp_commit();
    }
    cp_wait0();
    __syncthreads();

    // ---- load Q fragments into registers
    uint32_t qah[4][4], qal[4][4];
#pragma unroll
    for (int ks = 0; ks < 4; ks++) {
        const uint32_t swA = ((2 * ks + aU) ^ rxa) << 4;
        ldmx4(qah[ks], sb +         aoff + swA);
        ldmx4(qal[ks], sb + 16384 + aoff + swA);
    }
    __syncthreads(); // all warps done with Q smem; region becomes K/V buffers

    // ---- K/V staging geometry: 64 rows, 2 cp16 per tile per thread
    const int sRowK = t >> 2, uBK = (t & 3) * 2;
    auto stage_kv = [&](int bufI, int kbase) {
        const size_t rb = (size_t)(b * SS + kbase + sRowK) * DD + hoff;
        const uint32_t o = bufI * 8192;
#pragma unroll
        for (int i = 0; i < 2; i++) {
            int u = uBK + i;
            uint32_t sw = sRowK * 128 + ((u ^ (sRowK & 7)) << 4);
            cp16(sb + ASM_KH + o + sw, Kh_ + rb + u * 8);
            cp16(sb + ASM_KL + o + sw, Kl_ + rb + u * 8);
            cp16(sb + ASM_VH + o + sw, Vh_ + rb + u * 8);
            cp16(sb + ASM_VL + o + sw, Vl_ + rb + u * 8);
        }
    };
    stage_kv(0, 0);
    cp_commit();

    float m0 = -1e30f, m1 = -1e30f, l0 = 0.f, l1 = 0.f;
    float oacc[8][4];
#pragma unroll
    for (int j = 0; j < 8; j++)
#pragma unroll
        for (int r = 0; r < 4; r++) oacc[j][r] = 0.f;

    int buf = 0;
    for (int kb = 0; kb < nb; kb++) {
        cp_wait0();
        __syncthreads();
        if (kb + 1 < nb) {
            stage_kv(buf ^ 1, (kb + 1) * 64);
            cp_commit();
        }

        const uint32_t tKH = sb + ASM_KH + buf * 8192;
        const uint32_t tKL = sb + ASM_KL + buf * 8192;

        // ---- S2 = (QK^T) in exp2 domain (Q pre-scaled by 0.125*log2e)
        float sacc[8][4];
#pragma unroll
        for (int j = 0; j < 8; j++)
#pragma unroll
            for (int r = 0; r < 4; r++) sacc[j][r] = 0.f;
#pragma unroll
        for (int ks = 0; ks < 4; ks++) {
            uint32_t bh[8][2], bl[8][2];
#pragma unroll
            for (int jp = 0; jp < 4; jp++) {
                const uint32_t addr = (rowB + 16 * jp) * 128 + (((2 * ks + bU) ^ rxb) << 4);
                uint32_t r4[4];
                ldmx4(r4, tKH + addr);
                bh[2 * jp][0] = r4[0]; bh[2 * jp][1] = r4[1];
                bh[2 * jp + 1][0] = r4[2]; bh[2 * jp + 1][1] = r4[3];
                ldmx4(r4, tKL + addr);
                bl[2 * jp][0] = r4[0]; bl[2 * jp][1] = r4[1];
                bl[2 * jp + 1][0] = r4[2]; bl[2 * jp + 1][1] = r4[3];
            }
#pragma unroll
            for (int j = 0; j < 8; j++) {
                mma_bf16(sacc[j], qah[ks], bh[j]);
                mma_bf16(sacc[j], qah[ks], bl[j]);
                mma_bf16(sacc[j], qal[ks], bh[j]);
            }
        }

        // ---- mask tail keys
        const int kcol = kb * 64 + 2 * (lane & 3);
#pragma unroll
        for (int j = 0; j < 8; j++) {
            const int kc = kcol + 8 * j;
            if (kc >= cnt)     { sacc[j][0] = -1e30f; sacc[j][2] = -1e30f; }
            if (kc + 1 >= cnt) { sacc[j][1] = -1e30f; sacc[j][3] = -1e30f; }
        }

        // ---- online softmax (base-2)
        float rm0 = -1e30f, rm1 = -1e30f;
#pragma unroll
        for (int j = 0; j < 8; j++) {
            rm0 = fmaxf(rm0, fmaxf(sacc[j][0], sacc[j][1]));
            rm1 = fmaxf(rm1, fmaxf(sacc[j][2], sacc[j][3]));
        }
        rm0 = fmaxf(rm0, __shfl_xor_sync(0xffffffffu, rm0, 1));
        rm0 = fmaxf(rm0, __shfl_xor_sync(0xffffffffu, rm0, 2));
        rm1 = fmaxf(rm1, __shfl_xor_sync(0xffffffffu, rm1, 1));
        rm1 = fmaxf(rm1, __shfl_xor_sync(0xffffffffu, rm1, 2));
        const float nm0 = fmaxf(m0, rm0), nm1 = fmaxf(m1, rm1);
        const float c0 = ex2(m0 - nm0), c1 = ex2(m1 - nm1);
        m0 = nm0; m1 = nm1;
        float rs0 = 0.f, rs1 = 0.f;
#pragma unroll
        for (int j = 0; j < 8; j++) {
            sacc[j][0] = ex2(sacc[j][0] - nm0);
            sacc[j][1] = ex2(sacc[j][1] - nm0);
            sacc[j][2] = ex2(sacc[j][2] - nm1);
            sacc[j][3] = ex2(sacc[j][3] - nm1);
            rs0 += sacc[j][0] + sacc[j][1];
            rs1 += sacc[j][2] + sacc[j][3];
        }
        rs0 += __shfl_xor_sync(0xffffffffu, rs0, 1);
        rs0 += __shfl_xor_sync(0xffffffffu, rs0, 2);
        rs1 += __shfl_xor_sync(0xffffffffu, rs1, 1);
        rs1 += __shfl_xor_sync(0xffffffffu, rs1, 2);
        l0 = l0 * c0 + rs0;
        l1 = l1 * c1 + rs1;
#pragma unroll
        for (int j = 0; j < 8; j++) {
            oacc[j][0] *= c0; oacc[j][1] *= c0;
            oacc[j][2] *= c1; oacc[j][3] *= c1;
        }

        // ---- O += P V (hi/lo; V via ldmatrix trans)
        const uint32_t tVH = sb + ASM_VH + buf * 8192;
        const uint32_t tVL = sb + ASM_VL + buf * 8192;
#pragma unroll
        for (int ks = 0; ks < 4; ks++) {
            const int nt0 = 2 * ks, nt1 = 2 * ks + 1;
            uint32_t aPh[4], aPl[4];
            {
                float p00 = sacc[nt0][0], p01 = sacc[nt0][1];
                float p02 = sacc[nt0][2], p03 = sacc[nt0][3];
                float p10 = sacc[nt1][0], p11 = sacc[nt1][1];
                float p12 = sacc[nt1][2], p13 = sacc[nt1][3];
                __nv_bfloat16 h00 = __float2bfloat16(p00), h01 = __float2bfloat16(p01);
                __nv_bfloat16 h02 = __float2bfloat16(p02), h03 = __float2bfloat16(p03);
                __nv_bfloat16 h10 = __float2bfloat16(p10), h11 = __float2bfloat16(p11);
                __nv_bfloat16 h12 = __float2bfloat16(p12), h13 = __float2bfloat16(p13);
                __nv_bfloat162 v0(h00, h01), v1(h02, h03), v2(h10, h11), v3(h12, h13);
                aPh[0] = *(uint32_t*)&v0; aPh[1] = *(uint32_t*)&v1;
                aPh[2] = *(uint32_t*)&v2; aPh[3] = *(uint32_t*)&v3;
                aPl[0] = pack_bf16(p00 - __bfloat162float(h00), p01 - __bfloat162float(h01));
                aPl[1] = pack_bf16(p02 - __bfloat162float(h02), p03 - __bfloat162float(h03));
                aPl[2] = pack_bf16(p10 - __bfloat162float(h10), p11 - __bfloat162float(h11));
                aPl[3] = pack_bf16(p12 - __bfloat162float(h12), p13 - __bfloat162float(h13));
            }
            uint32_t bvh[8][2], bvl[8][2];
#pragma unroll
            for (int dp = 0; dp < 4; dp++) {
                const uint32_t addr = (rowV + 16 * ks) * 128 + (((2 * dp + vU) ^ rxv) << 4);
                uint32_t r4[4];
                ldmx4t(r4, tVH + addr);
                bvh[2 * dp][0] = r4[0]; bvh[2 * dp][1] = r4[1];
                bvh[2 * dp + 1][0] = r4[2]; bvh[2 * dp + 1][1] = r4[3];
                ldmx4t(r4, tVL + addr);
                bvl[2 * dp][0] = r4[0]; bvl[2 * dp][1] = r4[1];
                bvl[2 * dp + 1][0] = r4[2]; bvl[2 * dp + 1][1] = r4[3];
            }
#pragma unroll
            for (int j = 0; j < 8; j++) {
                mma_bf16(oacc[j], aPh, bvh[j]);
                mma_bf16(oacc[j], aPh, bvl[j]);
                mma_bf16(oacc[j], aPl, bvh[j]);
            }
        }
        buf ^= 1;
    }

    // ---- epilogue
    const float inv0 = 1.0f / l0, inv1 = 1.0f / l1;
    const int row0 = b * SS + q0 + w * 16 + (lane >> 2);
    const int row1 = row0 + 8;
    const int dbase = h * HDIM + 2 * (lane & 3);
#pragma unroll
    for (int j = 0; j < 8; j++) {
        float o00 = oacc[j][0] * inv0, o01 = oacc[j][1] * inv0;
        float o10 = oacc[j][2] * inv1, o11 = oacc[j][3] * inv1;
        __nv_bfloat16 h00 = __float2bfloat16(o00), h01 = __float2bfloat16(o01);
        __nv_bfloat16 h10 = __float2bfloat16(o10), h11 = __float2bfloat16(o11);
        size_t a0 = (size_t)row0 * DD + dbase + 8 * j;
        size_t a1 = (size_t)row1 * DD + dbase + 8 * j;
        *(__nv_bfloat162*)&Oh_[a0] = __nv_bfloat162(h00, h01);
        *(__nv_bfloat162*)&Ol_[a0] = __nv_bfloat162(
            __float2bfloat16(o00 - __bfloat162float(h00)),
            __float2bfloat16(o01 - __bfloat162float(h01)));
        *(__nv_bfloat162*)&Oh_[a1] = __nv_bfloat162(h10, h11);
        *(__nv_bfloat162*)&Ol_[a1] = __nv_bfloat162(
            __float2bfloat16(o10 - __bfloat162float(h10)),
            __float2bfloat16(o11 - __bfloat162float(h11)));
    }
}

// ---------------------------------------------------------------------------
// Launch
// ---------------------------------------------------------------------------
extern "C" void kernel_launch(void* const* d_in, const int* in_sizes, int n_in,
                              void* d_out, int out_size)
{
    (void)out_size;
    const float* qkv[3]   = {nullptr, nullptr, nullptr};
    const int*   masks[2] = {nullptr, nullptr};
    const float* Ws[4]    = {nullptr, nullptr, nullptr, nullptr};
    const float* bs[4]    = {nullptr, nullptr, nullptr, nullptr};
    int nqkv = 0, nmask = 0, nW = 0, nb = 0;
    for (int i = 0; i < n_in; i++) {
        int sz = in_sizes[i];
        if (sz == MTOT * DD && nqkv < 3)      qkv[nqkv++] = (const float*)d_in[i];
        else if (sz == MTOT && nmask < 2)     masks[nmask++] = (const int*)d_in[i];
        else if (sz == DD * DD && nW < 4)     Ws[nW++] = (const float*)d_in[i];
        else if (sz == DD && nb < 4)          bs[nb++] = (const float*)d_in[i];
    }

    static int attr_done = 0;
    if (!attr_done) {
        cudaFuncSetAttribute(gemm_mma_kernel,
                             cudaFuncAttributeMaxDynamicSharedMemorySize, GSM_BYTES);
        cudaFuncSetAttribute(attn_mma_kernel,
                             cudaFuncAttributeMaxDynamicSharedMemorySize, ATTN_SMEM);
        attr_done = 1;
    }

    int *gidx, *gcnt;
    __nv_bfloat16 *qh, *ql, *kh, *kl, *vh, *vl, *wh, *wl;
    __nv_bfloat16 *pqh, *pql, *pkh, *pkl, *pvh, *pvl, *ah, *al;
    cudaGetSymbolAddress((void**)&gidx, g_idx);
    cudaGetSymbolAddress((void**)&gcnt, g_cnt);
    cudaGetSymbolAddress((void**)&qh, g_qh); cudaGetSymbolAddress((void**)&ql, g_ql);
    cudaGetSymbolAddress((void**)&kh, g_kh); cudaGetSymbolAddress((void**)&kl, g_kl);
    cudaGetSymbolAddress((void**)&vh, g_vh); cudaGetSymbolAddress((void**)&vl, g_vl);
    cudaGetSymbolAddress((void**)&wh, g_Wh); cudaGetSymbolAddress((void**)&wl, g_Wl);
    cudaGetSymbolAddress((void**)&pqh, g_pqh); cudaGetSymbolAddress((void**)&pql, g_pql);
    cudaGetSymbolAddress((void**)&pkh, g_pkh); cudaGetSymbolAddress((void**)&pkl, g_pkl);
    cudaGetSymbolAddress((void**)&pvh, g_pvh); cudaGetSymbolAddress((void**)&pvl, g_pvl);
    cudaGetSymbolAddress((void**)&ah, g_ah);   cudaGetSymbolAddress((void**)&al, g_al);

    const int N8_ACT = MTOT * DD / 8;
    const int N8_W   = DD * DD / 8;
    dim3 mmaGrid(DD / 128, MTOT / 128); // (8, 32)

    build_idx_kernel<<<BB, 1024>>>(masks[0], masks[1], gidx, gcnt);

    conv_split_kernel<<<(N8_ACT + 255) / 256, 256>>>(qkv[0], qh, ql, N8_ACT);
    conv_split_kernel<<<(N8_ACT + 255) / 256, 256>>>(qkv[1], kh, kl, N8_ACT);
    conv_split_kernel<<<(N8_ACT + 255) / 256, 256>>>(qkv[2], vh, vl, N8_ACT);
    for (int w = 0; w < 4; w++)
        conv_split_kernel<<<(N8_W + 255) / 256, 256>>>(
            Ws[w], wh + (size_t)w * DD * DD, wl + (size_t)w * DD * DD, N8_W);

    // projections (Q pre-scaled by 0.125 * log2(e) for exp2-domain softmax)
    const float QSCALE = 0.125f * 1.4426950408889634f;
    gemm_mma_kernel<<<mmaGrid, 256, GSM_BYTES>>>(qh, ql, wh, wl, bs[0], QSCALE,
                                                 nullptr, pqh, pql, nullptr, nullptr);
    gemm_mma_kernel<<<mmaGrid, 256, GSM_BYTES>>>(kh, kl, wh + (size_t)1 * DD * DD,
                                                 wl + (size_t)1 * DD * DD, bs[1], 1.0f,
                                                 nullptr, pkh, pkl, gidx, gcnt);
    gemm_mma_kernel<<<mmaGrid, 256, GSM_BYTES>>>(vh, vl, wh + (size_t)2 * DD * DD,
                                                 wl + (size_t)2 * DD * DD, bs[2], 1.0f,
                                                 nullptr, pvh, pvl, gidx, gcnt);

    attn_mma_kernel<<<dim3(SS / 128, HH, BB), 256, ATTN_SMEM>>>(
        pqh, pql, pkh, pkl, pvh, pvl, ah, al, gcnt);

    gemm_mma_kernel<<<mmaGrid, 256, GSM_BYTES>>>(ah, al, wh + (size_t)3 * DD * DD,
                                                 wl + (size_t)3 * DD * DD, bs[3], 1.0f,
                                                 (float*)d_out, nullptr, nullptr,
                                                 nullptr, nullptr);
}

// round 8
// speedup vs baseline: 2.9971x; 1.1052x over previous
#include <cuda_runtime.h>
#include <cuda_bf16.h>
#include <cstdint>
#include <cstddef>

// Problem constants
#define BB 2
#define SS 2048
#define DD 1024
#define HH 16
#define HDIM 64
#define MTOT (BB * SS) // 4096

#define ACT ((size_t)MTOT * DD)  // 4194304 elements
#define WN  ((size_t)DD * DD)    // 1048576 elements

// ---------------------------------------------------------------------------
// Scratch (device globals). hi/lo pairs are contiguous: lo = hi + ACT (or WN).
// ---------------------------------------------------------------------------
__device__ int g_idx[MTOT];
__device__ int g_cnt[BB];
__device__ __nv_bfloat16 g_q[2 * MTOT * DD];
__device__ __nv_bfloat16 g_k[2 * MTOT * DD];
__device__ __nv_bfloat16 g_v[2 * MTOT * DD];
__device__ __nv_bfloat16 g_W[4][2 * DD * DD];
__device__ __nv_bfloat16 g_pq[2 * MTOT * DD];
__device__ __nv_bfloat16 g_pk[2 * MTOT * DD];
__device__ __nv_bfloat16 g_pv[2 * MTOT * DD];
__device__ __nv_bfloat16 g_a[2 * MTOT * DD];

// ---------------------------------------------------------------------------
// PTX helpers
// ---------------------------------------------------------------------------
__device__ __forceinline__ void cp16(unsigned dst, const void* src) {
    asm volatile("cp.async.cg.shared.global [%0], [%1], 16;" :: "r"(dst), "l"(src));
}
__device__ __forceinline__ void cp_commit() { asm volatile("cp.async.commit_group;"); }
__device__ __forceinline__ void cp_wait0()  { asm volatile("cp.async.wait_group 0;" ::: "memory"); }

__device__ __forceinline__ void ldmx4(uint32_t* r, uint32_t addr) {
    asm volatile("ldmatrix.sync.aligned.m8n8.x4.shared.b16 {%0,%1,%2,%3}, [%4];"
                 : "=r"(r[0]), "=r"(r[1]), "=r"(r[2]), "=r"(r[3]) : "r"(addr));
}
__device__ __forceinline__ void ldmx4t(uint32_t* r, uint32_t addr) {
    asm volatile("ldmatrix.sync.aligned.m8n8.x4.trans.shared.b16 {%0,%1,%2,%3}, [%4];"
                 : "=r"(r[0]), "=r"(r[1]), "=r"(r[2]), "=r"(r[3]) : "r"(addr));
}
__device__ __forceinline__ void mma_bf16(float* d, const uint32_t* a, const uint32_t* b) {
    asm volatile(
        "mma.sync.aligned.m16n8k16.row.col.f32.bf16.bf16.f32 "
        "{%0,%1,%2,%3}, {%4,%5,%6,%7}, {%8,%9}, {%0,%1,%2,%3};"
        : "+f"(d[0]), "+f"(d[1]), "+f"(d[2]), "+f"(d[3])
        : "r"(a[0]), "r"(a[1]), "r"(a[2]), "r"(a[3]), "r"(b[0]), "r"(b[1]));
}
__device__ __forceinline__ uint32_t pack_bf16(float a, float b) {
    __nv_bfloat162 v(__float2bfloat16(a), __float2bfloat16(b));
    return *(uint32_t*)&v;
}
__device__ __forceinline__ float ex2(float x) {
    float r;
    asm("ex2.approx.f32 %0, %1;" : "=f"(r) : "f"(x));
    return r;
}

// ---------------------------------------------------------------------------
// Kernel: fp32 -> bf16 (hi, lo) split, 8 elements/thread (16B stores)
// ---------------------------------------------------------------------------
__global__ __launch_bounds__(256) void conv_split_kernel(
    const float* __restrict__ x, __nv_bfloat16* __restrict__ hi,
    __nv_bfloat16* __restrict__ lo, int n8)
{
    int i = blockIdx.x * blockDim.x + threadIdx.x;
    if (i >= n8) return;
    float4 v0 = ((const float4*)x)[2 * i];
    float4 v1 = ((const float4*)x)[2 * i + 1];
    float f[8] = {v0.x, v0.y, v0.z, v0.w, v1.x, v1.y, v1.z, v1.w};
    uint32_t hp[4], lp[4];
#pragma unroll
    for (int j = 0; j < 4; j++) {
        __nv_bfloat16 h0 = __float2bfloat16(f[2 * j]);
        __nv_bfloat16 h1 = __float2bfloat16(f[2 * j + 1]);
        __nv_bfloat162 hv(h0, h1);
        hp[j] = *(uint32_t*)&hv;
        lp[j] = pack_bf16(f[2 * j] - __bfloat162float(h0),
                          f[2 * j + 1] - __bfloat162float(h1));
    }
    ((uint4*)hi)[i] = make_uint4(hp[0], hp[1], hp[2], hp[3]);
    ((uint4*)lo)[i] = make_uint4(lp[0], lp[1], lp[2], lp[3]);
}

// ---------------------------------------------------------------------------
// Kernel 1: deterministic mask compaction
// ---------------------------------------------------------------------------
__global__ __launch_bounds__(1024) void build_idx_kernel(
    const int* __restrict__ kp, const int* __restrict__ am,
    int* __restrict__ idx, int* __restrict__ counts)
{
    __shared__ int ssum[1024];
    const int b = blockIdx.x;
    const int t = threadIdx.x;
    const int base = b * SS;
    const int s0 = 2 * t, s1 = 2 * t + 1;
    int v0 = (kp[base + s0] == 0 && am[base + s0] == 0) ? 1 : 0;
    int v1 = (kp[base + s1] == 0 && am[base + s1] == 0) ? 1 : 0;
    ssum[t] = v0 + v1;
    __syncthreads();
    for (int off = 1; off < 1024; off <<= 1) {
        int add = (t >= off) ? ssum[t - off] : 0;
        int val = ssum[t];
        __syncthreads();
        ssum[t] = val + add;
        __syncthreads();
    }
    int excl = ssum[t] - (v0 + v1);
    if (v0) idx[base + excl]      = base + s0;
    if (v1) idx[base + excl + v0] = base + s1;
    if (t == 1023) counts[b] = ssum[1023];
}

// ---------------------------------------------------------------------------
// Kernel 2: HMMA GEMM, tile 256x128, BK=64, 512 threads (16 warps, 32x64/warp)
// 2-stage smem pipeline, 96KB/stage (AH 32K | AL 32K | WH 16K | WL 16K).
// grid.z selects operand set (combined Q/K/V launch); gmask bit z = use gather.
// W traffic halves vs 128x128 tiles (16 m-blocks instead of 32).
// ---------------------------------------------------------------------------
#define GSTAGE2 98304
#define GSM2_BYTES (2 * GSTAGE2)

__global__ __launch_bounds__(512, 1) void gemm_mma_kernel(
    const __nv_bfloat16* __restrict__ A0, const __nv_bfloat16* __restrict__ A1,
    const __nv_bfloat16* __restrict__ A2,
    const __nv_bfloat16* __restrict__ Wb,     // weight z at Wb + z*2*WN; lo at +WN
    const float* __restrict__ b0, const float* __restrict__ b1,
    const float* __restrict__ b2,
    float s0,
    float* __restrict__ Cf,                   // fp32 out (O projection)
    __nv_bfloat16* __restrict__ C0, __nv_bfloat16* __restrict__ C1,
    __nv_bfloat16* __restrict__ C2,           // bf16 out hi; lo at +ACT
    const int* __restrict__ gather, const int* __restrict__ counts, int gmask)
{
    extern __shared__ char smem[];
    const uint32_t sb = (uint32_t)__cvta_generic_to_shared(smem);
    const int z = blockIdx.z;
    const __nv_bfloat16* Ahi = (z == 0) ? A0 : (z == 1) ? A1 : A2;
    const __nv_bfloat16* Bhi = Wb + (size_t)z * 2 * WN;
    const float* bias = (z == 0) ? b0 : (z == 1) ? b1 : b2;
    __nv_bfloat16* Chi = (z == 0) ? C0 : (z == 1) ? C1 : C2;
    const float scale = (z == 0) ? s0 : 1.0f;
    const bool useG = ((gmask >> z) & 1) != 0;

    const int nBase = blockIdx.x * 128;
    const int mBase = blockIdx.y * 256;
    int cnt = 0;
    if (useG) {
        cnt = counts[mBase >> 11];
        if ((mBase & 2047) >= cnt) return;
    }
    const int t = threadIdx.x;
    const int wid = t >> 5, lane = t & 31;
    const int wm = wid >> 1;   // 0..7 -> m offset wm*32
    const int wn = wid & 1;    // 0..1 -> n offset wn*64

    // A staging: row t>>1 (0..255), units (t&1)*4 + i
    const int sRow = t >> 1, uA = (t & 1) * 4;
    int srcRow;
    {
        int m = mBase + sRow;
        if (useG) {
            bool ok = (m & 2047) < cnt;
            srcRow = ok ? gather[m] : ((m >> 11) * SS); // safe dummy row
        } else {
            srcRow = m;
        }
    }
    const __nv_bfloat16* aHp = Ahi + (size_t)srcRow * DD;
    // W staging: row t>>2 (0..127), units (t&3)*2 + i
    const int sRowW = t >> 2, uW = (t & 3) * 2;
    const __nv_bfloat16* bHp = Bhi + (size_t)(nBase + sRowW) * DD;

    // fragment geometry
    const int g  = lane >> 3;
    const int lr = lane & 7;
    const uint32_t rowA = wm * 32 + (g & 1) * 8 + lr;   // + mt*16 via +2048B
    const uint32_t rxa  = rowA & 7;
    const uint32_t aoff = rowA * 128;
    const int aU = g >> 1;
    const uint32_t rowB = wn * 64 + (g >> 1) * 8 + lr;  // + jp*16 via +2048B
    const uint32_t rxb  = rowB & 7;
    const uint32_t boff = rowB * 128;
    const int bU = g & 1;

    float acc[2][8][4];
#pragma unroll
    for (int mt = 0; mt < 2; mt++)
#pragma unroll
        for (int j = 0; j < 8; j++)
#pragma unroll
            for (int r = 0; r < 4; r++) acc[mt][j][r] = 0.f;

    // stage chunk k0 into stage s
    auto stage = [&](int s, int k0) {
        const uint32_t bb = sb + s * GSTAGE2;
#pragma unroll
        for (int i = 0; i < 4; i++) {
            int u = uA + i;
            uint32_t sw = sRow * 128 + ((u ^ (sRow & 7)) << 4);
            cp16(bb +         sw, aHp + k0 + u * 8);
            cp16(bb + 32768 + sw, aHp + ACT + k0 + u * 8);
        }
#pragma unroll
        for (int i = 0; i < 2; i++) {
            int u = uW + i;
            uint32_t sw = sRowW * 128 + ((u ^ (sRowW & 7)) << 4);
            cp16(bb + 65536 + sw, bHp + k0 + u * 8);
            cp16(bb + 81920 + sw, bHp + WN + k0 + u * 8);
        }
        cp_commit();
    };
    stage(0, 0);

    for (int c = 0; c < 16; c++) {
        cp_wait0();
        __syncthreads();
        if (c + 1 < 16) stage((c + 1) & 1, (c + 1) * 64);

        const uint32_t base = sb + (c & 1) * GSTAGE2;
#pragma unroll
        for (int ks = 0; ks < 4; ks++) {
            uint32_t ah[2][4], al[2][4];
#pragma unroll
            for (int mt = 0; mt < 2; mt++) {
                uint32_t sw = ((2 * ks + aU) ^ rxa) << 4;
                ldmx4(ah[mt], base +         aoff + mt * 2048 + sw);
                ldmx4(al[mt], base + 32768 + aoff + mt * 2048 + sw);
            }
#pragma unroll
            for (int jp = 0; jp < 4; jp++) {
                uint32_t sw = ((2 * ks + bU) ^ rxb) << 4;
                uint32_t rh[4], rl[4];
                ldmx4(rh, base + 65536 + boff + jp * 2048 + sw);
                ldmx4(rl, base + 81920 + boff + jp * 2048 + sw);
                // rh = { j=2jp:k0-7, j=2jp:k8-15, j=2jp+1:k0-7, j=2jp+1:k8-15 }
#pragma unroll
                for (int mt = 0; mt < 2; mt++) {
                    mma_bf16(acc[mt][2 * jp],     ah[mt], rh);
                    mma_bf16(acc[mt][2 * jp],     ah[mt], rl);
                    mma_bf16(acc[mt][2 * jp],     al[mt], rh);
                    mma_bf16(acc[mt][2 * jp + 1], ah[mt], rh + 2);
                    mma_bf16(acc[mt][2 * jp + 1], ah[mt], rl + 2);
                    mma_bf16(acc[mt][2 * jp + 1], al[mt], rh + 2);
                }
            }
        }
        __syncthreads();
    }

    // epilogue
#pragma unroll
    for (int mt = 0; mt < 2; mt++) {
        int m0 = mBase + wm * 32 + mt * 16 + (lane >> 2);
        int m1 = m0 + 8;
        bool ok0 = true, ok1 = true;
        if (useG) {
            ok0 = (m0 & 2047) < cnt;
            ok1 = (m1 & 2047) < cnt;
        }
#pragma unroll
        for (int j = 0; j < 8; j++) {
            int n = nBase + wn * 64 + j * 8 + 2 * (lane & 3);
            float b0v = bias[n], b1v = bias[n + 1];
            float o00 = (acc[mt][j][0] + b0v) * scale;
            float o01 = (acc[mt][j][1] + b1v) * scale;
            float o10 = (acc[mt][j][2] + b0v) * scale;
            float o11 = (acc[mt][j][3] + b1v) * scale;
            if (Cf) {
                if (ok0) *(float2*)&Cf[(size_t)m0 * DD + n] = make_float2(o00, o01);
                if (ok1) *(float2*)&Cf[(size_t)m1 * DD + n] = make_float2(o10, o11);
            } else {
                if (ok0) {
                    __nv_bfloat16 h0 = __float2bfloat16(o00), h1 = __float2bfloat16(o01);
                    *(__nv_bfloat162*)&Chi[(size_t)m0 * DD + n] = __nv_bfloat162(h0, h1);
                    *(__nv_bfloat162*)&Chi[ACT + (size_t)m0 * DD + n] = __nv_bfloat162(
                        __float2bfloat16(o00 - __bfloat162float(h0)),
                        __float2bfloat16(o01 - __bfloat162float(h1)));
                }
                if (ok1) {
                    __nv_bfloat16 h0 = __float2bfloat16(o10), h1 = __float2bfloat16(o11);
                    *(__nv_bfloat162*)&Chi[(size_t)m1 * DD + n] = __nv_bfloat162(h0, h1);
                    *(__nv_bfloat162*)&Chi[ACT + (size_t)m1 * DD + n] = __nv_bfloat162(
                        __float2bfloat16(o10 - __bfloat162float(h0)),
                        __float2bfloat16(o11 - __bfloat162float(h1)));
                }
            }
        }
    }
}

// ---------------------------------------------------------------------------
// Kernel 3: tensor-core flash attention (unchanged from round 7)
// ---------------------------------------------------------------------------
#define ASM_KH 0
#define ASM_KL 16384
#define ASM_VH 32768
#define ASM_VL 49152
#define ATTN_SMEM 65536

__global__ __launch_bounds__(256) void attn_mma_kernel(
    const __nv_bfloat16* __restrict__ Qh_, const __nv_bfloat16* __restrict__ Ql_,
    const __nv_bfloat16* __restrict__ Kh_, const __nv_bfloat16* __restrict__ Kl_,
    const __nv_bfloat16* __restrict__ Vh_, const __nv_bfloat16* __restrict__ Vl_,
    __nv_bfloat16* __restrict__ Oh_, __nv_bfloat16* __restrict__ Ol_,
    const int* __restrict__ counts)
{
    extern __shared__ char smem[];
    const uint32_t sb = (uint32_t)__cvta_generic_to_shared(smem);
    const int qb = blockIdx.x, h = blockIdx.y, b = blockIdx.z;
    const int t = threadIdx.x, w = t >> 5, lane = t & 31;
    const int q0 = qb * 128;
    const int cnt = counts[b];
    const int nb = (cnt + 63) >> 6;
    const size_t hoff = (size_t)h * HDIM;

    const int g  = lane >> 3;
    const int lr = lane & 7;
    const uint32_t rowA = w * 16 + (g & 1) * 8 + lr;
    const uint32_t rxa  = rowA & 7;
    const uint32_t aoff = rowA * 128;
    const int aU = g >> 1;
    const uint32_t rowB = (g >> 1) * 8 + lr;
    const uint32_t rxb  = rowB & 7;
    const int bU = g & 1;
    const uint32_t rowV = (g & 1) * 8 + lr;
    const uint32_t rxv  = rowV & 7;
    const int vU = g >> 1;

    {
        const int sRowQ = t >> 1, uBQ = (t & 1) * 4;
        const __nv_bfloat16* qhp = Qh_ + (size_t)(b * SS + q0 + sRowQ) * DD + hoff;
        const __nv_bfloat16* qlp = Ql_ + (size_t)(b * SS + q0 + sRowQ) * DD + hoff;
#pragma unroll
        for (int i = 0; i < 4; i++) {
            int u = uBQ + i;
            uint32_t off = sRowQ * 128 + ((u ^ (sRowQ & 7)) << 4);
            cp16(sb + off,         qhp + u * 8);
            cp16(sb + 16384 + off, qlp + u * 8);
        }
        cp_commit();
    }
    cp_wait0();
    __syncthreads();

    uint32_t qah[4][4], qal[4][4];
#pragma unroll
    for (int ks = 0; ks < 4; ks++) {
        const uint32_t swA = ((2 * ks + aU) ^ rxa) << 4;
        ldmx4(qah[ks], sb +         aoff + swA);
        ldmx4(qal[ks], sb + 16384 + aoff + swA);
    }
    __syncthreads();

    const int sRowK = t >> 2, uBK = (t & 3) * 2;
    auto stage_kv = [&](int bufI, int kbase) {
        const size_t rb = (size_t)(b * SS + kbase + sRowK) * DD + hoff;
        const uint32_t o = bufI * 8192;
#pragma unroll
        for (int i = 0; i < 2; i++) {
            int u = uBK + i;
            uint32_t sw = sRowK * 128 + ((u ^ (sRowK & 7)) << 4);
            cp16(sb + ASM_KH + o + sw, Kh_ + rb + u * 8);
            cp16(sb + ASM_KL + o + sw, Kl_ + rb + u * 8);
            cp16(sb + ASM_VH + o + sw, Vh_ + rb + u * 8);
            cp16(sb + ASM_VL + o + sw, Vl_ + rb + u * 8);
        }
    };
    stage_kv(0, 0);
    cp_commit();

    float m0 = -1e30f, m1 = -1e30f, l0 = 0.f, l1 = 0.f;
    float oacc[8][4];
#pragma unroll
    for (int j = 0; j < 8; j++)
#pragma unroll
        for (int r = 0; r < 4; r++) oacc[j][r] = 0.f;

    int buf = 0;
    for (int kb = 0; kb < nb; kb++) {
        cp_wait0();
        __syncthreads();
        if (kb + 1 < nb) {
            stage_kv(buf ^ 1, (kb + 1) * 64);
            cp_commit();
        }

        const uint32_t tKH = sb + ASM_KH + buf * 8192;
        const uint32_t tKL = sb + ASM_KL + buf * 8192;

        float sacc[8][4];
#pragma unroll
        for (int j = 0; j < 8; j++)
#pragma unroll
            for (int r = 0; r < 4; r++) sacc[j][r] = 0.f;
#pragma unroll
        for (int ks = 0; ks < 4; ks++) {
            uint32_t bh[8][2], bl[8][2];
#pragma unroll
            for (int jp = 0; jp < 4; jp++) {
                const uint32_t addr = (rowB + 16 * jp) * 128 + (((2 * ks + bU) ^ rxb) << 4);
                uint32_t r4[4];
                ldmx4(r4, tKH + addr);
                bh[2 * jp][0] = r4[0]; bh[2 * jp][1] = r4[1];
                bh[2 * jp + 1][0] = r4[2]; bh[2 * jp + 1][1] = r4[3];
                ldmx4(r4, tKL + addr);
                bl[2 * jp][0] = r4[0]; bl[2 * jp][1] = r4[1];
                bl[2 * jp + 1][0] = r4[2]; bl[2 * jp + 1][1] = r4[3];
            }
#pragma unroll
            for (int j = 0; j < 8; j++) {
                mma_bf16(sacc[j], qah[ks], bh[j]);
                mma_bf16(sacc[j], qah[ks], bl[j]);
                mma_bf16(sacc[j], qal[ks], bh[j]);
            }
        }

        const int kcol = kb * 64 + 2 * (lane & 3);
#pragma unroll
        for (int j = 0; j < 8; j++) {
            const int kc = kcol + 8 * j;
            if (kc >= cnt)     { sacc[j][0] = -1e30f; sacc[j][2] = -1e30f; }
            if (kc + 1 >= cnt) { sacc[j][1] = -1e30f; sacc[j][3] = -1e30f; }
        }

        float rm0 = -1e30f, rm1 = -1e30f;
#pragma unroll
        for (int j = 0; j < 8; j++) {
            rm0 = fmaxf(rm0, fmaxf(sacc[j][0], sacc[j][1]));
            rm1 = fmaxf(rm1, fmaxf(sacc[j][2], sacc[j][3]));
        }
        rm0 = fmaxf(rm0, __shfl_xor_sync(0xffffffffu, rm0, 1));
        rm0 = fmaxf(rm0, __shfl_xor_sync(0xffffffffu, rm0, 2));
        rm1 = fmaxf(rm1, __shfl_xor_sync(0xffffffffu, rm1, 1));
        rm1 = fmaxf(rm1, __shfl_xor_sync(0xffffffffu, rm1, 2));
        const float nm0 = fmaxf(m0, rm0), nm1 = fmaxf(m1, rm1);
        const float c0 = ex2(m0 - nm0), c1 = ex2(m1 - nm1);
        m0 = nm0; m1 = nm1;
        float rs0 = 0.f, rs1 = 0.f;
#pragma unroll
        for (int j = 0; j < 8; j++) {
            sacc[j][0] = ex2(sacc[j][0] - nm0);
            sacc[j][1] = ex2(sacc[j][1] - nm0);
            sacc[j][2] = ex2(sacc[j][2] - nm1);
            sacc[j][3] = ex2(sacc[j][3] - nm1);
            rs0 += sacc[j][0] + sacc[j][1];
            rs1 += sacc[j][2] + sacc[j][3];
        }
        rs0 += __shfl_xor_sync(0xffffffffu, rs0, 1);
        rs0 += __shfl_xor_sync(0xffffffffu, rs0, 2);
        rs1 += __shfl_xor_sync(0xffffffffu, rs1, 1);
        rs1 += __shfl_xor_sync(0xffffffffu, rs1, 2);
        l0 = l0 * c0 + rs0;
        l1 = l1 * c1 + rs1;
#pragma unroll
        for (int j = 0; j < 8; j++) {
            oacc[j][0] *= c0; oacc[j][1] *= c0;
            oacc[j][2] *= c1; oacc[j][3] *= c1;
        }

        const uint32_t tVH = sb + ASM_VH + buf * 8192;
        const uint32_t tVL = sb + ASM_VL + buf * 8192;
#pragma unroll
        for (int ks = 0; ks < 4; ks++) {
            const int nt0 = 2 * ks, nt1 = 2 * ks + 1;
            uint32_t aPh[4], aPl[4];
            {
                float p00 = sacc[nt0][0], p01 = sacc[nt0][1];
                float p02 = sacc[nt0][2], p03 = sacc[nt0][3];
                float p10 = sacc[nt1][0], p11 = sacc[nt1][1];
                float p12 = sacc[nt1][2], p13 = sacc[nt1][3];
                __nv_bfloat16 h00 = __float2bfloat16(p00), h01 = __float2bfloat16(p01);
                __nv_bfloat16 h02 = __float2bfloat16(p02), h03 = __float2bfloat16(p03);
                __nv_bfloat16 h10 = __float2bfloat16(p10), h11 = __float2bfloat16(p11);
                __nv_bfloat16 h12 = __float2bfloat16(p12), h13 = __float2bfloat16(p13);
                __nv_bfloat162 v0(h00, h01), v1(h02, h03), v2(h10, h11), v3(h12, h13);
                aPh[0] = *(uint32_t*)&v0; aPh[1] = *(uint32_t*)&v1;
                aPh[2] = *(uint32_t*)&v2; aPh[3] = *(uint32_t*)&v3;
                aPl[0] = pack_bf16(p00 - __bfloat162float(h00), p01 - __bfloat162float(h01));
                aPl[1] = pack_bf16(p02 - __bfloat162float(h02), p03 - __bfloat162float(h03));
                aPl[2] = pack_bf16(p10 - __bfloat162float(h10), p11 - __bfloat162float(h11));
                aPl[3] = pack_bf16(p12 - __bfloat162float(h12), p13 - __bfloat162float(h13));
            }
            uint32_t bvh[8][2], bvl[8][2];
#pragma unroll
            for (int dp = 0; dp < 4; dp++) {
                const uint32_t addr = (rowV + 16 * ks) * 128 + (((2 * dp + vU) ^ rxv) << 4);
                uint32_t r4[4];
                ldmx4t(r4, tVH + addr);
                bvh[2 * dp][0] = r4[0]; bvh[2 * dp][1] = r4[1];
                bvh[2 * dp + 1][0] = r4[2]; bvh[2 * dp + 1][1] = r4[3];
                ldmx4t(r4, tVL + addr);
                bvl[2 * dp][0] = r4[0]; bvl[2 * dp][1] = r4[1];
                bvl[2 * dp + 1][0] = r4[2]; bvl[2 * dp + 1][1] = r4[3];
            }
#pragma unroll
            for (int j = 0; j < 8; j++) {
                mma_bf16(oacc[j], aPh, bvh[j]);
                mma_bf16(oacc[j], aPh, bvl[j]);
                mma_bf16(oacc[j], aPl, bvh[j]);
            }
        }
        buf ^= 1;
    }

    const float inv0 = 1.0f / l0, inv1 = 1.0f / l1;
    const int row0 = b * SS + q0 + w * 16 + (lane >> 2);
    const int row1 = row0 + 8;
    const int dbase = h * HDIM + 2 * (lane & 3);
#pragma unroll
    for (int j = 0; j < 8; j++) {
        float o00 = oacc[j][0] * inv0, o01 = oacc[j][1] * inv0;
        float o10 = oacc[j][2] * inv1, o11 = oacc[j][3] * inv1;
        __nv_bfloat16 h00 = __float2bfloat16(o00), h01 = __float2bfloat16(o01);
        __nv_bfloat16 h10 = __float2bfloat16(o10), h11 = __float2bfloat16(o11);
        size_t a0 = (size_t)row0 * DD + dbase + 8 * j;
        size_t a1 = (size_t)row1 * DD + dbase + 8 * j;
        *(__nv_bfloat162*)&Oh_[a0] = __nv_bfloat162(h00, h01);
        *(__nv_bfloat162*)&Ol_[a0] = __nv_bfloat162(
            __float2bfloat16(o00 - __bfloat162float(h00)),
            __float2bfloat16(o01 - __bfloat162float(h01)));
        *(__nv_bfloat162*)&Oh_[a1] = __nv_bfloat162(h10, h11);
        *(__nv_bfloat162*)&Ol_[a1] = __nv_bfloat162(
            __float2bfloat16(o10 - __bfloat162float(h10)),
            __float2bfloat16(o11 - __bfloat162float(h11)));
    }
}

// ---------------------------------------------------------------------------
// Launch
// ---------------------------------------------------------------------------
extern "C" void kernel_launch(void* const* d_in, const int* in_sizes, int n_in,
                              void* d_out, int out_size)
{
    (void)out_size;
    const float* qkv[3]   = {nullptr, nullptr, nullptr};
    const int*   masks[2] = {nullptr, nullptr};
    const float* Ws[4]    = {nullptr, nullptr, nullptr, nullptr};
    const float* bs[4]    = {nullptr, nullptr, nullptr, nullptr};
    int nqkv = 0, nmask = 0, nW = 0, nb = 0;
    for (int i = 0; i < n_in; i++) {
        int sz = in_sizes[i];
        if (sz == MTOT * DD && nqkv < 3)      qkv[nqkv++] = (const float*)d_in[i];
        else if (sz == MTOT && nmask < 2)     masks[nmask++] = (const int*)d_in[i];
        else if (sz == DD * DD && nW < 4)     Ws[nW++] = (const float*)d_in[i];
        else if (sz == DD && nb < 4)          bs[nb++] = (const float*)d_in[i];
    }

    static int attr_done = 0;
    if (!attr_done) {
        cudaFuncSetAttribute(gemm_mma_kernel,
                             cudaFuncAttributeMaxDynamicSharedMemorySize, GSM2_BYTES);
        cudaFuncSetAttribute(attn_mma_kernel,
                             cudaFuncAttributeMaxDynamicSharedMemorySize, ATTN_SMEM);
        attr_done = 1;
    }

    int *gidx, *gcnt;
    __nv_bfloat16 *gq, *gk, *gv, *gW, *gpq, *gpk, *gpv, *ga;
    cudaGetSymbolAddress((void**)&gidx, g_idx);
    cudaGetSymbolAddress((void**)&gcnt, g_cnt);
    cudaGetSymbolAddress((void**)&gq, g_q);
    cudaGetSymbolAddress((void**)&gk, g_k);
    cudaGetSymbolAddress((void**)&gv, g_v);
    cudaGetSymbolAddress((void**)&gW, g_W);
    cudaGetSymbolAddress((void**)&gpq, g_pq);
    cudaGetSymbolAddress((void**)&gpk, g_pk);
    cudaGetSymbolAddress((void**)&gpv, g_pv);
    cudaGetSymbolAddress((void**)&ga, g_a);

    const int N8_ACT = (int)(ACT / 8);
    const int N8_W   = (int)(WN / 8);

    build_idx_kernel<<<BB, 1024>>>(masks[0], masks[1], gidx, gcnt);

    conv_split_kernel<<<(N8_ACT + 255) / 256, 256>>>(qkv[0], gq, gq + ACT, N8_ACT);
    conv_split_kernel<<<(N8_ACT + 255) / 256, 256>>>(qkv[1], gk, gk + ACT, N8_ACT);
    conv_split_kernel<<<(N8_ACT + 255) / 256, 256>>>(qkv[2], gv, gv + ACT, N8_ACT);
    for (int w = 0; w < 4; w++)
        conv_split_kernel<<<(N8_W + 255) / 256, 256>>>(
            Ws[w], gW + (size_t)w * 2 * WN, gW + (size_t)w * 2 * WN + WN, N8_W);

    // combined Q/K/V projections (grid.z selects set; K/V gathered)
    const float QSCALE = 0.125f * 1.4426950408889634f;
    gemm_mma_kernel<<<dim3(DD / 128, MTOT / 256, 3), 512, GSM2_BYTES>>>(
        gq, gk, gv, gW, bs[0], bs[1], bs[2], QSCALE,
        nullptr, gpq, gpk, gpv, gidx, gcnt, 0b110);

    attn_mma_kernel<<<dim3(SS / 128, HH, BB), 256, ATTN_SMEM>>>(
        gpq, gpq + ACT, gpk, gpk + ACT, gpv, gpv + ACT, ga, ga + ACT, gcnt);

    // output projection -> fp32 d_out
    gemm_mma_kernel<<<dim3(DD / 128, MTOT / 256, 1), 512, GSM2_BYTES>>>(
        ga, ga, ga, gW + (size_t)3 * 2 * WN, bs[3], bs[3], bs[3], 1.0f,
        (float*)d_out, nullptr, nullptr, nullptr, nullptr, nullptr, 0);
}

// round 11
// speedup vs baseline: 3.0490x; 1.0173x over previous
#include <cuda_runtime.h>
#include <cuda_bf16.h>
#include <cstdint>
#include <cstddef>

// Problem constants
#define BB 2
#define SS 2048
#define DD 1024
#define HH 16
#define HDIM 64
#define MTOT (BB * SS) // 4096

#define ACT ((size_t)MTOT * DD)  // 4194304 elements
#define WN  ((size_t)DD * DD)    // 1048576 elements

// ---------------------------------------------------------------------------
// Scratch (device globals). hi/lo pairs are contiguous: lo = hi + ACT (or WN).
// ---------------------------------------------------------------------------
__device__ int g_idx[MTOT];
__device__ int g_cnt[BB];
__device__ __nv_bfloat16 g_q[2 * MTOT * DD];
__device__ __nv_bfloat16 g_k[2 * MTOT * DD];
__device__ __nv_bfloat16 g_v[2 * MTOT * DD];
__device__ __nv_bfloat16 g_W[4][2 * DD * DD];
__device__ __nv_bfloat16 g_pq[2 * MTOT * DD];
__device__ __nv_bfloat16 g_pk[2 * MTOT * DD];
__device__ __nv_bfloat16 g_pv[2 * MTOT * DD];
__device__ __nv_bfloat16 g_a[2 * MTOT * DD];

// ---------------------------------------------------------------------------
// PTX helpers
// ---------------------------------------------------------------------------
__device__ __forceinline__ void cp16(unsigned dst, const void* src) {
    asm volatile("cp.async.cg.shared.global [%0], [%1], 16;" :: "r"(dst), "l"(src));
}
__device__ __forceinline__ void cp_commit() { asm volatile("cp.async.commit_group;"); }
__device__ __forceinline__ void cp_wait0()  { asm volatile("cp.async.wait_group 0;" ::: "memory"); }

__device__ __forceinline__ void ldmx4(uint32_t* r, uint32_t addr) {
    asm volatile("ldmatrix.sync.aligned.m8n8.x4.shared.b16 {%0,%1,%2,%3}, [%4];"
                 : "=r"(r[0]), "=r"(r[1]), "=r"(r[2]), "=r"(r[3]) : "r"(addr));
}
__device__ __forceinline__ void ldmx4t(uint32_t* r, uint32_t addr) {
    asm volatile("ldmatrix.sync.aligned.m8n8.x4.trans.shared.b16 {%0,%1,%2,%3}, [%4];"
                 : "=r"(r[0]), "=r"(r[1]), "=r"(r[2]), "=r"(r[3]) : "r"(addr));
}
__device__ __forceinline__ void mma_bf16(float* d, const uint32_t* a, const uint32_t* b) {
    asm volatile(
        "mma.sync.aligned.m16n8k16.row.col.f32.bf16.bf16.f32 "
        "{%0,%1,%2,%3}, {%4,%5,%6,%7}, {%8,%9}, {%0,%1,%2,%3};"
        : "+f"(d[0]), "+f"(d[1]), "+f"(d[2]), "+f"(d[3])
        : "r"(a[0]), "r"(a[1]), "r"(a[2]), "r"(a[3]), "r"(b[0]), "r"(b[1]));
}
__device__ __forceinline__ uint32_t pack_bf16(float a, float b) {
    __nv_bfloat162 v(__float2bfloat16(a), __float2bfloat16(b));
    return *(uint32_t*)&v;
}
__device__ __forceinline__ float ex2(float x) {
    float r;
    asm("ex2.approx.f32 %0, %1;" : "=f"(r) : "f"(x));
    return r;
}

// ---------------------------------------------------------------------------
// Kernel: batched fp32 -> bf16 (hi, lo) split; blockIdx.y selects tensor
// ---------------------------------------------------------------------------
struct ConvArgs {
    const float* src[4];
    __nv_bfloat16* hi[4];
    __nv_bfloat16* lo[4];
};

__global__ __launch_bounds__(256) void conv_split_multi(ConvArgs a, int n8)
{
    int i = blockIdx.x * blockDim.x + threadIdx.x;
    if (i >= n8) return;
    const int y = blockIdx.y;
    const float* x = a.src[y];
    float4 v0 = ((const float4*)x)[2 * i];
    float4 v1 = ((const float4*)x)[2 * i + 1];
    float f[8] = {v0.x, v0.y, v0.z, v0.w, v1.x, v1.y, v1.z, v1.w};
    uint32_t hp[4], lp[4];
#pragma unroll
    for (int j = 0; j < 4; j++) {
        __nv_bfloat16 h0 = __float2bfloat16(f[2 * j]);
        __nv_bfloat16 h1 = __float2bfloat16(f[2 * j + 1]);
        __nv_bfloat162 hv(h0, h1);
        hp[j] = *(uint32_t*)&hv;
        lp[j] = pack_bf16(f[2 * j] - __bfloat162float(h0),
                          f[2 * j + 1] - __bfloat162float(h1));
    }
    ((uint4*)a.hi[y])[i] = make_uint4(hp[0], hp[1], hp[2], hp[3]);
    ((uint4*)a.lo[y])[i] = make_uint4(lp[0], lp[1], lp[2], lp[3]);
}

// ---------------------------------------------------------------------------
// Kernel 1: deterministic mask compaction
// ---------------------------------------------------------------------------
__global__ __launch_bounds__(1024) void build_idx_kernel(
    const int* __restrict__ kp, const int* __restrict__ am,
    int* __restrict__ idx, int* __restrict__ counts)
{
    __shared__ int ssum[1024];
    const int b = blockIdx.x;
    const int t = threadIdx.x;
    const int base = b * SS;
    const int s0 = 2 * t, s1 = 2 * t + 1;
    int v0 = (kp[base + s0] == 0 && am[base + s0] == 0) ? 1 : 0;
    int v1 = (kp[base + s1] == 0 && am[base + s1] == 0) ? 1 : 0;
    ssum[t] = v0 + v1;
    __syncthreads();
    for (int off = 1; off < 1024; off <<= 1) {
        int add = (t >= off) ? ssum[t - off] : 0;
        int val = ssum[t];
        __syncthreads();
        ssum[t] = val + add;
        __syncthreads();
    }
    int excl = ssum[t] - (v0 + v1);
    if (v0) idx[base + excl]      = base + s0;
    if (v1) idx[base + excl + v0] = base + s1;
    if (t == 1023) counts[b] = ssum[1023];
}

// ---------------------------------------------------------------------------
// Kernel 2: HMMA GEMM, tile 256x128, BK=64, 512 threads (16 warps, 32x64/warp)
// 2-stage smem pipeline, 96KB/stage. grid.z selects operand set.
// ---------------------------------------------------------------------------
#define GSTAGE2 98304
#define GSM2_BYTES (2 * GSTAGE2)

__global__ __launch_bounds__(512, 1) void gemm_mma_kernel(
    const __nv_bfloat16* __restrict__ A0, const __nv_bfloat16* __restrict__ A1,
    const __nv_bfloat16* __restrict__ A2,
    const __nv_bfloat16* __restrict__ Wb,
    const float* __restrict__ b0, const float* __restrict__ b1,
    const float* __restrict__ b2,
    float s0,
    float* __restrict__ Cf,
    __nv_bfloat16* __restrict__ C0, __nv_bfloat16* __restrict__ C1,
    __nv_bfloat16* __restrict__ C2,
    const int* __restrict__ gather, const int* __restrict__ counts, int gmask)
{
    extern __shared__ char smem[];
    const uint32_t sb = (uint32_t)__cvta_generic_to_shared(smem);
    const int z = blockIdx.z;
    const __nv_bfloat16* Ahi = (z == 0) ? A0 : (z == 1) ? A1 : A2;
    const __nv_bfloat16* Bhi = Wb + (size_t)z * 2 * WN;
    const float* bias = (z == 0) ? b0 : (z == 1) ? b1 : b2;
    __nv_bfloat16* Chi = (z == 0) ? C0 : (z == 1) ? C1 : C2;
    const float scale = (z == 0) ? s0 : 1.0f;
    const bool useG = ((gmask >> z) & 1) != 0;

    const int nBase = blockIdx.x * 128;
    const int mBase = blockIdx.y * 256;
    int cnt = 0;
    if (useG) {
        cnt = counts[mBase >> 11];
        if ((mBase & 2047) >= cnt) return;
    }
    const int t = threadIdx.x;
    const int wid = t >> 5, lane = t & 31;
    const int wm = wid >> 1;
    const int wn = wid & 1;

    const int sRow = t >> 1, uA = (t & 1) * 4;
    int srcRow;
    {
        int m = mBase + sRow;
        if (useG) {
            bool ok = (m & 2047) < cnt;
            srcRow = ok ? gather[m] : ((m >> 11) * SS);
        } else {
            srcRow = m;
        }
    }
    const __nv_bfloat16* aHp = Ahi + (size_t)srcRow * DD;
    const int sRowW = t >> 2, uW = (t & 3) * 2;
    const __nv_bfloat16* bHp = Bhi + (size_t)(nBase + sRowW) * DD;

    const int g  = lane >> 3;
    const int lr = lane & 7;
    const uint32_t rowA = wm * 32 + (g & 1) * 8 + lr;
    const uint32_t rxa  = rowA & 7;
    const uint32_t aoff = rowA * 128;
    const int aU = g >> 1;
    const uint32_t rowB = wn * 64 + (g >> 1) * 8 + lr;
    const uint32_t rxb  = rowB & 7;
    const uint32_t boff = rowB * 128;
    const int bU = g & 1;

    float acc[2][8][4];
#pragma unroll
    for (int mt = 0; mt < 2; mt++)
#pragma unroll
        for (int j = 0; j < 8; j++)
#pragma unroll
            for (int r = 0; r < 4; r++) acc[mt][j][r] = 0.f;

    auto stage = [&](int s, int k0) {
        const uint32_t bb = sb + s * GSTAGE2;
#pragma unroll
        for (int i = 0; i < 4; i++) {
            int u = uA + i;
            uint32_t sw = sRow * 128 + ((u ^ (sRow & 7)) << 4);
            cp16(bb +         sw, aHp + k0 + u * 8);
            cp16(bb + 32768 + sw, aHp + ACT + k0 + u * 8);
        }
#pragma unroll
        for (int i = 0; i < 2; i++) {
            int u = uW + i;
            uint32_t sw = sRowW * 128 + ((u ^ (sRowW & 7)) << 4);
            cp16(bb + 65536 + sw, bHp + k0 + u * 8);
            cp16(bb + 81920 + sw, bHp + WN + k0 + u * 8);
        }
        cp_commit();
    };
    stage(0, 0);

    for (int c = 0; c < 16; c++) {
        cp_wait0();
        __syncthreads();
        if (c + 1 < 16) stage((c + 1) & 1, (c + 1) * 64);

        const uint32_t base = sb + (c & 1) * GSTAGE2;
#pragma unroll
        for (int ks = 0; ks < 4; ks++) {
            uint32_t ah[2][4], al[2][4];
#pragma unroll
            for (int mt = 0; mt < 2; mt++) {
                uint32_t sw = ((2 * ks + aU) ^ rxa) << 4;
                ldmx4(ah[mt], base +         aoff + mt * 2048 + sw);
                ldmx4(al[mt], base + 32768 + aoff + mt * 2048 + sw);
            }
#pragma unroll
            for (int jp = 0; jp < 4; jp++) {
                uint32_t sw = ((2 * ks + bU) ^ rxb) << 4;
                uint32_t rh[4], rl[4];
                ldmx4(rh, base + 65536 + boff + jp * 2048 + sw);
                ldmx4(rl, base + 81920 + boff + jp * 2048 + sw);
#pragma unroll
                for (int mt = 0; mt < 2; mt++) {
                    mma_bf16(acc[mt][2 * jp],     ah[mt], rh);
                    mma_bf16(acc[mt][2 * jp],     ah[mt], rl);
                    mma_bf16(acc[mt][2 * jp],     al[mt], rh);
                    mma_bf16(acc[mt][2 * jp + 1], ah[mt], rh + 2);
                    mma_bf16(acc[mt][2 * jp + 1], ah[mt], rl + 2);
                    mma_bf16(acc[mt][2 * jp + 1], al[mt], rh + 2);
                }
            }
        }
        __syncthreads();
    }

#pragma unroll
    for (int mt = 0; mt < 2; mt++) {
        int m0 = mBase + wm * 32 + mt * 16 + (lane >> 2);
        int m1 = m0 + 8;
        bool ok0 = true, ok1 = true;
        if (useG) {
            ok0 = (m0 & 2047) < cnt;
            ok1 = (m1 & 2047) < cnt;
        }
#pragma unroll
        for (int j = 0; j < 8; j++) {
            int n = nBase + wn * 64 + j * 8 + 2 * (lane & 3);
            float b0v = bias[n], b1v = bias[n + 1];
            float o00 = (acc[mt][j][0] + b0v) * scale;
            float o01 = (acc[mt][j][1] + b1v) * scale;
            float o10 = (acc[mt][j][2] + b0v) * scale;
            float o11 = (acc[mt][j][3] + b1v) * scale;
            if (Cf) {
                if (ok0) *(float2*)&Cf[(size_t)m0 * DD + n] = make_float2(o00, o01);
                if (ok1) *(float2*)&Cf[(size_t)m1 * DD + n] = make_float2(o10, o11);
            } else {
                if (ok0) {
                    __nv_bfloat16 h0 = __float2bfloat16(o00), h1 = __float2bfloat16(o01);
                    *(__nv_bfloat162*)&Chi[(size_t)m0 * DD + n] = __nv_bfloat162(h0, h1);
                    *(__nv_bfloat162*)&Chi[ACT + (size_t)m0 * DD + n] = __nv_bfloat162(
                        __float2bfloat16(o00 - __bfloat162float(h0)),
                        __float2bfloat16(o01 - __bfloat162float(h1)));
                }
                if (ok1) {
                    __nv_bfloat16 h0 = __float2bfloat16(o10), h1 = __float2bfloat16(o11);
                    *(__nv_bfloat162*)&Chi[(size_t)m1 * DD + n] = __nv_bfloat162(h0, h1);
                    *(__nv_bfloat162*)&Chi[ACT + (size_t)m1 * DD + n] = __nv_bfloat162(
                        __float2bfloat16(o10 - __bfloat162float(h0)),
                        __float2bfloat16(o11 - __bfloat162float(h1)));
                }
            }
        }
    }
}

// ---------------------------------------------------------------------------
// Kernel 3: tensor-core flash attention (streamed B fragments, 2 CTAs/SM)
// ---------------------------------------------------------------------------
#define ASM_KH 0
#define ASM_KL 16384
#define ASM_VH 32768
#define ASM_VL 49152
#define ATTN_SMEM 65536

__global__ __launch_bounds__(256, 2) void attn_mma_kernel(
    const __nv_bfloat16* __restrict__ Qh_, const __nv_bfloat16* __restrict__ Ql_,
    const __nv_bfloat16* __restrict__ Kh_, const __nv_bfloat16* __restrict__ Kl_,
    const __nv_bfloat16* __restrict__ Vh_, const __nv_bfloat16* __restrict__ Vl_,
    __nv_bfloat16* __restrict__ Oh_, __nv_bfloat16* __restrict__ Ol_,
    const int* __restrict__ counts)
{
    extern __shared__ char smem[];
    const uint32_t sb = (uint32_t)__cvta_generic_to_shared(smem);
    const int qb = blockIdx.x, h = blockIdx.y, b = blockIdx.z;
    const int t = threadIdx.x, w = t >> 5, lane = t & 31;
    const int q0 = qb * 128;
    const int cnt = counts[b];
    const int nb = (cnt + 63) >> 6;
    const size_t hoff = (size_t)h * HDIM;

    const int g  = lane >> 3;
    const int lr = lane & 7;
    const uint32_t rowA = w * 16 + (g & 1) * 8 + lr;
    const uint32_t rxa  = rowA & 7;
    const uint32_t aoff = rowA * 128;
    const int aU = g >> 1;
    const uint32_t rowB = (g >> 1) * 8 + lr;
    const uint32_t rxb  = rowB & 7;
    const int bU = g & 1;
    const uint32_t rowV = (g & 1) * 8 + lr;
    const uint32_t rxv  = rowV & 7;
    const int vU = g >> 1;

    {
        const int sRowQ = t >> 1, uBQ = (t & 1) * 4;
        const __nv_bfloat16* qhp = Qh_ + (size_t)(b * SS + q0 + sRowQ) * DD + hoff;
        const __nv_bfloat16* qlp = Ql_ + (size_t)(b * SS + q0 + sRowQ) * DD + hoff;
#pragma unroll
        for (int i = 0; i < 4; i++) {
            int u = uBQ + i;
            uint32_t off = sRowQ * 128 + ((u ^ (sRowQ & 7)) << 4);
            cp16(sb + off,         qhp + u * 8);
            cp16(sb + 16384 + off, qlp + u * 8);
        }
        cp_commit();
    }
    cp_wait0();
    __syncthreads();

    uint32_t qah[4][4], qal[4][4];
#pragma unroll
    for (int ks = 0; ks < 4; ks++) {
        const uint32_t swA = ((2 * ks + aU) ^ rxa) << 4;
        ldmx4(qah[ks], sb +         aoff + swA);
        ldmx4(qal[ks], sb + 16384 + aoff + swA);
    }
    __syncthreads();

    const int sRowK = t >> 2, uBK = (t & 3) * 2;
    auto stage_kv = [&](int bufI, int kbase) {
        const size_t rb = (size_t)(b * SS + kbase + sRowK) * DD + hoff;
        const uint32_t o = bufI * 8192;
#pragma unroll
        for (int i = 0; i < 2; i++) {
            int u = uBK + i;
            uint32_t sw = sRowK * 128 + ((u ^ (sRowK & 7)) << 4);
            cp16(sb + ASM_KH + o + sw, Kh_ + rb + u * 8);
            cp16(sb + ASM_KL + o + sw, Kl_ + rb + u * 8);
            cp16(sb + ASM_VH + o + sw, Vh_ + rb + u * 8);
            cp16(sb + ASM_VL + o + sw, Vl_ + rb + u * 8);
        }
    };
    stage_kv(0, 0);
    cp_commit();

    float m0 = -1e30f, m1 = -1e30f, l0 = 0.f, l1 = 0.f;
    float oacc[8][4];
#pragma unroll
    for (int j = 0; j < 8; j++)
#pragma unroll
        for (int r = 0; r < 4; r++) oacc[j][r] = 0.f;

    int buf = 0;
    for (int kb = 0; kb < nb; kb++) {
        cp_wait0();
        __syncthreads();
        if (kb + 1 < nb) {
            stage_kv(buf ^ 1, (kb + 1) * 64);
            cp_commit();
        }

        const uint32_t tKH = sb + ASM_KH + buf * 8192;
        const uint32_t tKL = sb + ASM_KL + buf * 8192;

        // ---- S = Q K^T (hi/lo, streamed K fragments: 6 MMAs per jp)
        float sacc[8][4];
#pragma unroll
        for (int j = 0; j < 8; j++)
#pragma unroll
            for (int r = 0; r < 4; r++) sacc[j][r] = 0.f;
#pragma unroll
        for (int ks = 0; ks < 4; ks++) {
#pragma unroll
            for (int jp = 0; jp < 4; jp++) {
                const uint32_t addr = (rowB + 16 * jp) * 128 + (((2 * ks + bU) ^ rxb) << 4);
                uint32_t rh[4], rl[4];
                ldmx4(rh, tKH + addr);
                ldmx4(rl, tKL + addr);
                mma_bf16(sacc[2 * jp],     qah[ks], rh);
                mma_bf16(sacc[2 * jp],     qah[ks], rl);
                mma_bf16(sacc[2 * jp],     qal[ks], rh);
                mma_bf16(sacc[2 * jp + 1], qah[ks], rh + 2);
                mma_bf16(sacc[2 * jp + 1], qah[ks], rl + 2);
                mma_bf16(sacc[2 * jp + 1], qal[ks], rh + 2);
            }
        }

        const int kcol = kb * 64 + 2 * (lane & 3);
#pragma unroll
        for (int j = 0; j < 8; j++) {
            const int kc = kcol + 8 * j;
            if (kc >= cnt)     { sacc[j][0] = -1e30f; sacc[j][2] = -1e30f; }
            if (kc + 1 >= cnt) { sacc[j][1] = -1e30f; sacc[j][3] = -1e30f; }
        }

        float rm0 = -1e30f, rm1 = -1e30f;
#pragma unroll
        for (int j = 0; j < 8; j++) {
            rm0 = fmaxf(rm0, fmaxf(sacc[j][0], sacc[j][1]));
            rm1 = fmaxf(rm1, fmaxf(sacc[j][2], sacc[j][3]));
        }
        rm0 = fmaxf(rm0, __shfl_xor_sync(0xffffffffu, rm0, 1));
        rm0 = fmaxf(rm0, __shfl_xor_sync(0xffffffffu, rm0, 2));
        rm1 = fmaxf(rm1, __shfl_xor_sync(0xffffffffu, rm1, 1));
        rm1 = fmaxf(rm1, __shfl_xor_sync(0xffffffffu, rm1, 2));
        const float nm0 = fmaxf(m0, rm0), nm1 = fmaxf(m1, rm1);
        const float c0 = ex2(m0 - nm0), c1 = ex2(m1 - nm1);
        m0 = nm0; m1 = nm1;
        float rs0 = 0.f, rs1 = 0.f;
#pragma unroll
        for (int j = 0; j < 8; j++) {
            sacc[j][0] = ex2(sacc[j][0] - nm0);
            sacc[j][1] = ex2(sacc[j][1] - nm0);
            sacc[j][2] = ex2(sacc[j][2] - nm1);
            sacc[j][3] = ex2(sacc[j][3] - nm1);
            rs0 += sacc[j][0] + sacc[j][1];
            rs1 += sacc[j][2] + sacc[j][3];
        }
        rs0 += __shfl_xor_sync(0xffffffffu, rs0, 1);
        rs0 += __shfl_xor_sync(0xffffffffu, rs0, 2);
        rs1 += __shfl_xor_sync(0xffffffffu, rs1, 1);
        rs1 += __shfl_xor_sync(0xffffffffu, rs1, 2);
        l0 = l0 * c0 + rs0;
        l1 = l1 * c1 + rs1;
#pragma unroll
        for (int j = 0; j < 8; j++) {
            oacc[j][0] *= c0; oacc[j][1] *= c0;
            oacc[j][2] *= c1; oacc[j][3] *= c1;
        }

        // ---- O += P V (hi/lo, streamed V fragments: 6 MMAs per dp)
        const uint32_t tVH = sb + ASM_VH + buf * 8192;
        const uint32_t tVL = sb + ASM_VL + buf * 8192;
#pragma unroll
        for (int ks = 0; ks < 4; ks++) {
            const int nt0 = 2 * ks, nt1 = 2 * ks + 1;
            uint32_t aPh[4], aPl[4];
            {
                float p00 = sacc[nt0][0], p01 = sacc[nt0][1];
                float p02 = sacc[nt0][2], p03 = sacc[nt0][3];
                float p10 = sacc[nt1][0], p11 = sacc[nt1][1];
                float p12 = sacc[nt1][2], p13 = sacc[nt1][3];
                __nv_bfloat16 h00 = __float2bfloat16(p00), h01 = __float2bfloat16(p01);
                __nv_bfloat16 h02 = __float2bfloat16(p02), h03 = __float2bfloat16(p03);
                __nv_bfloat16 h10 = __float2bfloat16(p10), h11 = __float2bfloat16(p11);
                __nv_bfloat16 h12 = __float2bfloat16(p12), h13 = __float2bfloat16(p13);
                __nv_bfloat162 v0(h00, h01), v1(h02, h03), v2(h10, h11), v3(h12, h13);
                aPh[0] = *(uint32_t*)&v0; aPh[1] = *(uint32_t*)&v1;
                aPh[2] = *(uint32_t*)&v2; aPh[3] = *(uint32_t*)&v3;
                aPl[0] = pack_bf16(p00 - __bfloat162float(h00), p01 - __bfloat162float(h01));
                aPl[1] = pack_bf16(p02 - __bfloat162float(h02), p03 - __bfloat162float(h03));
                aPl[2] = pack_bf16(p10 - __bfloat162float(h10), p11 - __bfloat162float(h11));
                aPl[3] = pack_bf16(p12 - __bfloat162float(h12), p13 - __bfloat162float(h13));
            }
#pragma unroll
            for (int dp = 0; dp < 4; dp++) {
                const uint32_t addr = (rowV + 16 * ks) * 128 + (((2 * dp + vU) ^ rxv) << 4);
                uint32_t rvh[4], rvl[4];
                ldmx4t(rvh, tVH + addr);
                ldmx4t(rvl, tVL + addr);
                mma_bf16(oacc[2 * dp],     aPh, rvh);
                mma_bf16(oacc[2 * dp],     aPh, rvl);
                mma_bf16(oacc[2 * dp],     aPl, rvh);
                mma_bf16(oacc[2 * dp + 1], aPh, rvh + 2);
                mma_bf16(oacc[2 * dp + 1], aPh, rvl + 2);
                mma_bf16(oacc[2 * dp + 1], aPl, rvh + 2);
            }
        }
        buf ^= 1;
    }

    const float inv0 = 1.0f / l0, inv1 = 1.0f / l1;
    const int row0 = b * SS + q0 + w * 16 + (lane >> 2);
    const int row1 = row0 + 8;
    const int dbase = h * HDIM + 2 * (lane & 3);
#pragma unroll
    for (int j = 0; j < 8; j++) {
        float o00 = oacc[j][0] * inv0, o01 = oacc[j][1] * inv0;
        float o10 = oacc[j][2] * inv1, o11 = oacc[j][3] * inv1;
        __nv_bfloat16 h00 = __float2bfloat16(o00), h01 = __float2bfloat16(o01);
        __nv_bfloat16 h10 = __float2bfloat16(o10), h11 = __float2bfloat16(o11);
        size_t a0 = (size_t)row0 * DD + dbase + 8 * j;
        size_t a1 = (size_t)row1 * DD + dbase + 8 * j;
        *(__nv_bfloat162*)&Oh_[a0] = __nv_bfloat162(h00, h01);
        *(__nv_bfloat162*)&Ol_[a0] = __nv_bfloat162(
            __float2bfloat16(o00 - __bfloat162float(h00)),
            __float2bfloat16(o01 - __bfloat162float(h01)));
        *(__nv_bfloat162*)&Oh_[a1] = __nv_bfloat162(h10, h11);
        *(__nv_bfloat162*)&Ol_[a1] = __nv_bfloat162(
            __float2bfloat16(o10 - __bfloat162float(h10)),
            __float2bfloat16(o11 - __bfloat162float(h11)));
    }
}

// ---------------------------------------------------------------------------
// Launch
// ---------------------------------------------------------------------------
extern "C" void kernel_launch(void* const* d_in, const int* in_sizes, int n_in,
                              void* d_out, int out_size)
{
    (void)out_size;
    const float* qkv[3]   = {nullptr, nullptr, nullptr};
    const int*   masks[2] = {nullptr, nullptr};
    const float* Ws[4]    = {nullptr, nullptr, nullptr, nullptr};
    const float* bs[4]    = {nullptr, nullptr, nullptr, nullptr};
    int nqkv = 0, nmask = 0, nW = 0, nb = 0;
    for (int i = 0; i < n_in; i++) {
        int sz = in_sizes[i];
        if (sz == MTOT * DD && nqkv < 3)      qkv[nqkv++] = (const float*)d_in[i];
        else if (sz == MTOT && nmask < 2)     masks[nmask++] = (const int*)d_in[i];
        else if (sz == DD * DD && nW < 4)     Ws[nW++] = (const float*)d_in[i];
        else if (sz == DD && nb < 4)          bs[nb++] = (const float*)d_in[i];
    }

    static int attr_done = 0;
    if (!attr_done) {
        cudaFuncSetAttribute(gemm_mma_kernel,
                             cudaFuncAttributeMaxDynamicSharedMemorySize, GSM2_BYTES);
        cudaFuncSetAttribute(attn_mma_kernel,
                             cudaFuncAttributeMaxDynamicSharedMemorySize, ATTN_SMEM);
        attr_done = 1;
    }

    int *gidx, *gcnt;
    __nv_bfloat16 *gq, *gk, *gv, *gW, *gpq, *gpk, *gpv, *ga;
    cudaGetSymbolAddress((void**)&gidx, g_idx);
    cudaGetSymbolAddress((void**)&gcnt, g_cnt);
    cudaGetSymbolAddress((void**)&gq, g_q);
    cudaGetSymbolAddress((void**)&gk, g_k);
    cudaGetSymbolAddress((void**)&gv, g_v);
    cudaGetSymbolAddress((void**)&gW, g_W);
    cudaGetSymbolAddress((void**)&gpq, g_pq);
    cudaGetSymbolAddress((void**)&gpk, g_pk);
    cudaGetSymbolAddress((void**)&gpv, g_pv);
    cudaGetSymbolAddress((void**)&ga, g_a);

    const int N8_ACT = (int)(ACT / 8);
    const int N8_W   = (int)(WN / 8);

    build_idx_kernel<<<BB, 1024>>>(masks[0], masks[1], gidx, gcnt);

    // batched conv: 3 activations in one launch, 4 weights in another
    {
        ConvArgs aa = {};
        aa.src[0] = qkv[0]; aa.hi[0] = gq; aa.lo[0] = gq + ACT;
        aa.src[1] = qkv[1]; aa.hi[1] = gk; aa.lo[1] = gk + ACT;
        aa.src[2] = qkv[2]; aa.hi[2] = gv; aa.lo[2] = gv + ACT;
        conv_split_multi<<<dim3((N8_ACT + 255) / 256, 3), 256>>>(aa, N8_ACT);

        ConvArgs wa = {};
        for (int w = 0; w < 4; w++) {
            wa.src[w] = Ws[w];
            wa.hi[w]  = gW + (size_t)w * 2 * WN;
            wa.lo[w]  = gW + (size_t)w * 2 * WN + WN;
        }
        conv_split_multi<<<dim3((N8_W + 255) / 256, 4), 256>>>(wa, N8_W);
    }

    // combined Q/K/V projections (grid.z selects set; K/V gathered)
    const float QSCALE = 0.125f * 1.4426950408889634f;
    gemm_mma_kernel<<<dim3(DD / 128, MTOT / 256, 3), 512, GSM2_BYTES>>>(
        gq, gk, gv, gW, bs[0], bs[1], bs[2], QSCALE,
        nullptr, gpq, gpk, gpv, gidx, gcnt, 0b110);

    attn_mma_kernel<<<dim3(SS / 128, HH, BB), 256, ATTN_SMEM>>>(
        gpq, gpq + ACT, gpk, gpk + ACT, gpv, gpv + ACT, ga, ga + ACT, gcnt);

    // output projection -> fp32 d_out
    gemm_mma_kernel<<<dim3(DD / 128, MTOT / 256, 1), 512, GSM2_BYTES>>>(
        ga, ga, ga, gW + (size_t)3 * 2 * WN, bs[3], bs[3], bs[3], 1.0f,
        (float*)d_out, nullptr, nullptr, nullptr, nullptr, nullptr, 0);
}